// round 2
// baseline (speedup 1.0000x reference)
#include <cuda_runtime.h>

#define NROWS 8192
#define HID   256
#define BM    64
#define BN    64
#define NTHREADS 256

// scratch for projected Q, K, V (8 MB each; __device__ globals are the
// sanctioned scratch mechanism under the allocation guards)
__device__ float g_q[NROWS * HID];
__device__ float g_k[NROWS * HID];
__device__ float g_v[NROWS * HID];

typedef unsigned long long u64;

__device__ __forceinline__ u64 pk2(float x, float y) {
    u64 r; asm("mov.b64 %0, {%1,%2};" : "=l"(r) : "f"(x), "f"(y)); return r;
}
__device__ __forceinline__ void upk2(u64 v, float& x, float& y) {
    asm("mov.b64 {%0,%1}, %2;" : "=f"(x), "=f"(y) : "l"(v));
}
// packed fp32x2 FMA (sm_100+): doubles fp32 FMA throughput vs FFMA-3reg
__device__ __forceinline__ u64 fma2(u64 a, u64 b, u64 c) {
    u64 d; asm("fma.rn.f32x2 %0, %1, %2, %3;" : "=l"(d) : "l"(a), "l"(b), "l"(c)); return d;
}
__device__ __forceinline__ float sigmoidf_(float x) {
    return __frcp_rn(1.0f + __expf(-x));
}

// ---------------------------------------------------------------------------
// out[row, col] = X[row,:] . W[col,:] + bias[col]    (X: [8192,256], W: [256,256])
// 64x64 tile per CTA, 256 threads, 4 rows x 4 cols per thread (as 2 f32x2 pairs)
// ---------------------------------------------------------------------------
__global__ __launch_bounds__(NTHREADS)
void linear_kernel(const float* __restrict__ X, const float* __restrict__ W,
                   const float* __restrict__ bias, float* __restrict__ out)
{
    __shared__ float sX[32 * 64];   // [k][m]
    __shared__ float sW[32 * 64];   // [k][n]
    const int tid  = threadIdx.x;
    const int row0 = blockIdx.x * 64;
    const int col0 = blockIdx.y * 64;
    const int m0   = (tid >> 4) << 2;   // 0..60
    const int ac2  = (tid & 15) << 1;   // 0..30 (col pair base; 2nd pair at +32)
    const int lm   = tid & 63;
    const int lk   = (tid >> 6) << 3;

    u64 acc[4][2];
#pragma unroll
    for (int r = 0; r < 4; r++) { acc[r][0] = 0ull; acc[r][1] = 0ull; }

    const float* Xp = X + (row0 + lm) * HID + lk;
    const float* Wp = W + (col0 + lm) * HID + lk;

    for (int k0 = 0; k0 < HID; k0 += 32) {
        float4 xa = *(const float4*)(Xp + k0);
        float4 xb = *(const float4*)(Xp + k0 + 4);
        float4 wa = *(const float4*)(Wp + k0);
        float4 wb = *(const float4*)(Wp + k0 + 4);
        sX[(lk + 0) * 64 + lm] = xa.x; sX[(lk + 1) * 64 + lm] = xa.y;
        sX[(lk + 2) * 64 + lm] = xa.z; sX[(lk + 3) * 64 + lm] = xa.w;
        sX[(lk + 4) * 64 + lm] = xb.x; sX[(lk + 5) * 64 + lm] = xb.y;
        sX[(lk + 6) * 64 + lm] = xb.z; sX[(lk + 7) * 64 + lm] = xb.w;
        sW[(lk + 0) * 64 + lm] = wa.x; sW[(lk + 1) * 64 + lm] = wa.y;
        sW[(lk + 2) * 64 + lm] = wa.z; sW[(lk + 3) * 64 + lm] = wa.w;
        sW[(lk + 4) * 64 + lm] = wb.x; sW[(lk + 5) * 64 + lm] = wb.y;
        sW[(lk + 6) * 64 + lm] = wb.z; sW[(lk + 7) * 64 + lm] = wb.w;
        __syncthreads();
#pragma unroll
        for (int kk = 0; kk < 32; kk++) {
            float4 q = *(const float4*)(sX + kk * 64 + m0);
            u64 b0 = *(const u64*)(sW + kk * 64 + ac2);
            u64 b1 = *(const u64*)(sW + kk * 64 + ac2 + 32);
            u64 a;
            a = pk2(q.x, q.x); acc[0][0] = fma2(a, b0, acc[0][0]); acc[0][1] = fma2(a, b1, acc[0][1]);
            a = pk2(q.y, q.y); acc[1][0] = fma2(a, b0, acc[1][0]); acc[1][1] = fma2(a, b1, acc[1][1]);
            a = pk2(q.z, q.z); acc[2][0] = fma2(a, b0, acc[2][0]); acc[2][1] = fma2(a, b1, acc[2][1]);
            a = pk2(q.w, q.w); acc[3][0] = fma2(a, b0, acc[3][0]); acc[3][1] = fma2(a, b1, acc[3][1]);
        }
        __syncthreads();
    }
    const int c0 = col0 + ac2;
    const float b0 = bias[c0],      b1 = bias[c0 + 1];
    const float b2 = bias[c0 + 32], b3 = bias[c0 + 33];
#pragma unroll
    for (int r = 0; r < 4; r++) {
        float x, y;
        upk2(acc[r][0], x, y);
        *(float2*)(out + (row0 + m0 + r) * HID + c0) = make_float2(x + b0, y + b1);
        upk2(acc[r][1], x, y);
        *(float2*)(out + (row0 + m0 + r) * HID + c0 + 32) = make_float2(x + b2, y + b3);
    }
}

// ---------------------------------------------------------------------------
// Fused sigmoid attention: out[i,:] = sum_j sigmoid(q_i . k_j) * v_j
// CTA = 64 Q rows; loop over 8192 K/V rows in chunks of 64.
//   stage A: S = Q Kt (Q,K k-major in smem, f32x2 packed over col pairs)
//   sigmoid -> P stored transposed + column-duplicated: sP[j][2m]=sP[j][2m+1]=P[m][j]
//   stage B: acc(64x256) += P V, 8 rows x 8 cols per thread (all f32x2)
// smem: Q 64KB + K 64KB + V 64KB + P 33KB = 230400 B (dynamic, opt-in)
// ---------------------------------------------------------------------------
#define SQ_OFF 0
#define SK_OFF 16384
#define SV_OFF 32768
#define SP_OFF 49152
#define SP_STRIDE 132            // 128 used + pad; 132*4 % 16 == 0 for LDS.128
#define SMEM_FLOATS (49152 + BN * SP_STRIDE)   // 57600 floats = 230400 bytes

__global__ __launch_bounds__(NTHREADS)
void attn_kernel(float* __restrict__ out)
{
    extern __shared__ float smem[];
    float* sQ = smem + SQ_OFF;    // [k][m] 256x64
    float* sK = smem + SK_OFF;    // [k][j] 256x64
    float* sV = smem + SV_OFF;    // [j][c] 64x256
    float* sP = smem + SP_OFF;    // [j][2m dup] 64x132

    const int tid  = threadIdx.x;
    const int row0 = blockIdx.x * BM;
    const int lm   = tid & 63;
    const int lkb  = tid >> 6;    // 0..3

    // load Q tile transposed into sQ[k*64+m]
    {
        const float* gq = g_q + (row0 + lm) * HID;
#pragma unroll
        for (int kb = 0; kb < 4; kb++) {
            int k0 = (lkb + kb * 4) * 16;
#pragma unroll
            for (int j = 0; j < 4; j++) {
                float4 v = *(const float4*)(gq + k0 + j * 4);
                sQ[(k0 + j * 4 + 0) * 64 + lm] = v.x;
                sQ[(k0 + j * 4 + 1) * 64 + lm] = v.y;
                sQ[(k0 + j * 4 + 2) * 64 + lm] = v.z;
                sQ[(k0 + j * 4 + 3) * 64 + lm] = v.w;
            }
        }
    }

    const int ar0  = (tid >> 4) << 2;   // stage A rows
    const int ac2  = (tid & 15) << 1;   // stage A col-pair base
    const int warp = tid >> 5;
    const int lane = tid & 31;
    const int br2  = warp << 4;         // 2 * (warp*8): stage B row base in dup'd P
    const int cl2  = lane << 1;         // stage B col-pair base

    u64 accB[8][4];
#pragma unroll
    for (int r = 0; r < 8; r++)
#pragma unroll
        for (int i = 0; i < 4; i++) accB[r][i] = 0ull;

    for (int j0 = 0; j0 < NROWS; j0 += BN) {
        __syncthreads();   // previous iteration done with sK/sV/sP (covers sQ on iter 0)

        // load K chunk transposed
        {
            const float* gk = g_k + (j0 + lm) * HID;
#pragma unroll
            for (int kb = 0; kb < 4; kb++) {
                int k0 = (lkb + kb * 4) * 16;
#pragma unroll
                for (int j = 0; j < 4; j++) {
                    float4 v = *(const float4*)(gk + k0 + j * 4);
                    sK[(k0 + j * 4 + 0) * 64 + lm] = v.x;
                    sK[(k0 + j * 4 + 1) * 64 + lm] = v.y;
                    sK[(k0 + j * 4 + 2) * 64 + lm] = v.z;
                    sK[(k0 + j * 4 + 3) * 64 + lm] = v.w;
                }
            }
        }
        // load V chunk (row-major, coalesced float4)
        {
#pragma unroll
            for (int i = 0; i < 16; i++) {
                int f = tid + i * 256;          // float4 index within 64x256 tile
                int r = f >> 6;
                int c = (f & 63) << 2;
                *(float4*)(sV + r * 256 + c) = *(const float4*)(g_v + (j0 + r) * HID + c);
            }
        }
        __syncthreads();

        // ---- stage A: S[64][64] = Q . Kt over k=256 ----
        u64 a00 = 0, a01 = 0, a10 = 0, a11 = 0, a20 = 0, a21 = 0, a30 = 0, a31 = 0;
        const float* q_ptr = sQ + ar0;
        const float* k_ptr = sK + ac2;
#pragma unroll 8
        for (int kk = 0; kk < HID; kk++) {
            float4 q = *(const float4*)(q_ptr + kk * 64);
            u64 b0 = *(const u64*)(k_ptr + kk * 64);
            u64 b1 = *(const u64*)(k_ptr + kk * 64 + 32);
            u64 a;
            a = pk2(q.x, q.x); a00 = fma2(a, b0, a00); a01 = fma2(a, b1, a01);
            a = pk2(q.y, q.y); a10 = fma2(a, b0, a10); a11 = fma2(a, b1, a11);
            a = pk2(q.z, q.z); a20 = fma2(a, b0, a20); a21 = fma2(a, b1, a21);
            a = pk2(q.w, q.w); a30 = fma2(a, b0, a30); a31 = fma2(a, b1, a31);
        }
        // sigmoid + transposed duplicated store
        {
            float xs[4][4];
            upk2(a00, xs[0][0], xs[0][1]); upk2(a01, xs[0][2], xs[0][3]);
            upk2(a10, xs[1][0], xs[1][1]); upk2(a11, xs[1][2], xs[1][3]);
            upk2(a20, xs[2][0], xs[2][1]); upk2(a21, xs[2][2], xs[2][3]);
            upk2(a30, xs[3][0], xs[3][1]); upk2(a31, xs[3][2], xs[3][3]);
            const int ccol[4] = {ac2, ac2 + 1, ac2 + 32, ac2 + 33};
#pragma unroll
            for (int r = 0; r < 4; r++) {
#pragma unroll
                for (int c = 0; c < 4; c++) {
                    float s = sigmoidf_(xs[r][c]);
                    *(u64*)(sP + ccol[c] * SP_STRIDE + ((ar0 + r) << 1)) = pk2(s, s);
                }
            }
        }
        __syncthreads();

        // ---- stage B: acc += P V ----
        const float* p_base = sP + br2;
        const float* v_base = sV + cl2;
#pragma unroll 2
        for (int jj = 0; jj < BN; jj++) {
            const float* pr = p_base + jj * SP_STRIDE;
            ulonglong2 p01 = *(const ulonglong2*)(pr);       // (P[r0],P[r0]),(P[r1],P[r1])
            ulonglong2 p23 = *(const ulonglong2*)(pr + 4);
            ulonglong2 p45 = *(const ulonglong2*)(pr + 8);
            ulonglong2 p67 = *(const ulonglong2*)(pr + 12);
            const float* vr = v_base + jj * 256;
            u64 v0 = *(const u64*)(vr);
            u64 v1 = *(const u64*)(vr + 64);
            u64 v2 = *(const u64*)(vr + 128);
            u64 v3 = *(const u64*)(vr + 192);
            accB[0][0] = fma2(p01.x, v0, accB[0][0]); accB[0][1] = fma2(p01.x, v1, accB[0][1]);
            accB[0][2] = fma2(p01.x, v2, accB[0][2]); accB[0][3] = fma2(p01.x, v3, accB[0][3]);
            accB[1][0] = fma2(p01.y, v0, accB[1][0]); accB[1][1] = fma2(p01.y, v1, accB[1][1]);
            accB[1][2] = fma2(p01.y, v2, accB[1][2]); accB[1][3] = fma2(p01.y, v3, accB[1][3]);
            accB[2][0] = fma2(p23.x, v0, accB[2][0]); accB[2][1] = fma2(p23.x, v1, accB[2][1]);
            accB[2][2] = fma2(p23.x, v2, accB[2][2]); accB[2][3] = fma2(p23.x, v3, accB[2][3]);
            accB[3][0] = fma2(p23.y, v0, accB[3][0]); accB[3][1] = fma2(p23.y, v1, accB[3][1]);
            accB[3][2] = fma2(p23.y, v2, accB[3][2]); accB[3][3] = fma2(p23.y, v3, accB[3][3]);
            accB[4][0] = fma2(p45.x, v0, accB[4][0]); accB[4][1] = fma2(p45.x, v1, accB[4][1]);
            accB[4][2] = fma2(p45.x, v2, accB[4][2]); accB[4][3] = fma2(p45.x, v3, accB[4][3]);
            accB[5][0] = fma2(p45.y, v0, accB[5][0]); accB[5][1] = fma2(p45.y, v1, accB[5][1]);
            accB[5][2] = fma2(p45.y, v2, accB[5][2]); accB[5][3] = fma2(p45.y, v3, accB[5][3]);
            accB[6][0] = fma2(p67.x, v0, accB[6][0]); accB[6][1] = fma2(p67.x, v1, accB[6][1]);
            accB[6][2] = fma2(p67.x, v2, accB[6][2]); accB[6][3] = fma2(p67.x, v3, accB[6][3]);
            accB[7][0] = fma2(p67.y, v0, accB[7][0]); accB[7][1] = fma2(p67.y, v1, accB[7][1]);
            accB[7][2] = fma2(p67.y, v2, accB[7][2]); accB[7][3] = fma2(p67.y, v3, accB[7][3]);
        }
    }

    // epilogue: write 64x256 output tile
#pragma unroll
    for (int r = 0; r < 8; r++) {
        float* orow = out + (row0 + (warp << 3) + r) * HID + cl2;
        float x, y;
#pragma unroll
        for (int i = 0; i < 4; i++) {
            upk2(accB[r][i], x, y);
            *(float2*)(orow + i * 64) = make_float2(x, y);
        }
    }
}

// ---------------------------------------------------------------------------
extern "C" void kernel_launch(void* const* d_in, const int* in_sizes, int n_in,
                              void* d_out, int out_size)
{
    const float* query = (const float*)d_in[0];
    const float* key_  = (const float*)d_in[1];
    const float* value = (const float*)d_in[2];
    const float* Wq    = (const float*)d_in[3];
    const float* bq    = (const float*)d_in[4];
    const float* Wk    = (const float*)d_in[5];
    const float* bk    = (const float*)d_in[6];
    const float* Wv    = (const float*)d_in[7];
    const float* bv    = (const float*)d_in[8];
    float* out = (float*)d_out;
    (void)in_sizes; (void)n_in; (void)out_size;

    float *dq, *dk, *dv;
    cudaGetSymbolAddress((void**)&dq, g_q);
    cudaGetSymbolAddress((void**)&dk, g_k);
    cudaGetSymbolAddress((void**)&dv, g_v);

    dim3 lgrid(NROWS / 64, HID / 64);
    linear_kernel<<<lgrid, NTHREADS>>>(query, Wq, bq, dq);
    linear_kernel<<<lgrid, NTHREADS>>>(key_,  Wk, bk, dk);
    linear_kernel<<<lgrid, NTHREADS>>>(value, Wv, bv, dv);

    int smem_bytes = SMEM_FLOATS * (int)sizeof(float);   // 230400 <= 232448 opt-in max
    cudaFuncSetAttribute(attn_kernel, cudaFuncAttributeMaxDynamicSharedMemorySize, smem_bytes);
    attn_kernel<<<NROWS / BM, NTHREADS, smem_bytes>>>(out);
}

// round 5
// speedup vs baseline: 2.2204x; 2.2204x over previous
#include <cuda_runtime.h>
#include <cuda_bf16.h>
#include <cstdint>

#define NROWS 8192
#define HID   256
#define NTHREADS 256
#define BJ 64
#define NCHUNK (NROWS / BJ)

// ---------------- device scratch ----------------
__device__ float g_q[NROWS * HID];
__device__ float g_k[NROWS * HID];
__device__ float g_v[NROWS * HID];
__device__ __nv_bfloat16 g_qhi[NROWS * HID], g_qlo[NROWS * HID];
__device__ __nv_bfloat16 g_khi[NROWS * HID], g_klo[NROWS * HID];
__device__ __nv_bfloat16 g_vthi[HID * NROWS], g_vtlo[HID * NROWS]; // [hid][token]

typedef unsigned long long u64;
__device__ __forceinline__ u64 pk2(float x, float y) {
    u64 r; asm("mov.b64 %0, {%1,%2};" : "=l"(r) : "f"(x), "f"(y)); return r;
}
__device__ __forceinline__ void upk2(u64 v, float& x, float& y) {
    asm("mov.b64 {%0,%1}, %2;" : "=f"(x), "=f"(y) : "l"(v));
}
__device__ __forceinline__ u64 fma2(u64 a, u64 b, u64 c) {
    u64 d; asm("fma.rn.f32x2 %0, %1, %2, %3;" : "=l"(d) : "l"(a), "l"(b), "l"(c)); return d;
}
__device__ __forceinline__ float fsig(float x) {
    return __frcp_rn(1.0f + __expf(-x));
}
__device__ __forceinline__ void split2(float a, float b, uint32_t& hi, uint32_t& lo) {
    __nv_bfloat16 ha = __float2bfloat16(a), hb = __float2bfloat16(b);
    float ra = a - __bfloat162float(ha), rb = b - __bfloat162float(hb);
    hi = ((uint32_t)__bfloat16_as_ushort(hb) << 16) | (uint32_t)__bfloat16_as_ushort(ha);
    __nv_bfloat16 la = __float2bfloat16(ra), lb = __float2bfloat16(rb);
    lo = ((uint32_t)__bfloat16_as_ushort(lb) << 16) | (uint32_t)__bfloat16_as_ushort(la);
}
__device__ __forceinline__ uint32_t smem_to_u32(const void* p) {
    uint32_t a;
    asm("{ .reg .u64 t; cvta.to.shared.u64 t, %1; cvt.u32.u64 %0, t; }" : "=r"(a) : "l"(p));
    return a;
}
__device__ __forceinline__ void ldsm4(uint32_t r[4], uint32_t addr) {
    asm volatile("ldmatrix.sync.aligned.m8n8.x4.shared.b16 {%0,%1,%2,%3}, [%4];"
                 : "=r"(r[0]), "=r"(r[1]), "=r"(r[2]), "=r"(r[3]) : "r"(addr));
}
__device__ __forceinline__ void mma16816(float c[4], const uint32_t a[4], uint32_t b0, uint32_t b1) {
    asm volatile("mma.sync.aligned.m16n8k16.row.col.f32.bf16.bf16.f32 "
                 "{%0,%1,%2,%3}, {%4,%5,%6,%7}, {%8,%9}, {%0,%1,%2,%3};"
                 : "+f"(c[0]), "+f"(c[1]), "+f"(c[2]), "+f"(c[3])
                 : "r"(a[0]), "r"(a[1]), "r"(a[2]), "r"(a[3]), "r"(b0), "r"(b1));
}

// ---------------- fp32 linear (proven) ----------------
__global__ __launch_bounds__(NTHREADS)
void linear_kernel(const float* __restrict__ X, const float* __restrict__ W,
                   const float* __restrict__ bias, float* __restrict__ out)
{
    __shared__ float sX[32 * 64];
    __shared__ float sW[32 * 64];
    const int tid = threadIdx.x;
    const int row0 = blockIdx.x * 64, col0 = blockIdx.y * 64;
    const int m0 = (tid >> 4) << 2, ac2 = (tid & 15) << 1;
    const int lm = tid & 63, lk = (tid >> 6) << 3;
    u64 acc[4][2];
#pragma unroll
    for (int r = 0; r < 4; r++) { acc[r][0] = 0ull; acc[r][1] = 0ull; }
    const float* Xp = X + (row0 + lm) * HID + lk;
    const float* Wp = W + (col0 + lm) * HID + lk;
    for (int k0 = 0; k0 < HID; k0 += 32) {
        float4 xa = *(const float4*)(Xp + k0), xb = *(const float4*)(Xp + k0 + 4);
        float4 wa = *(const float4*)(Wp + k0), wb = *(const float4*)(Wp + k0 + 4);
        sX[(lk+0)*64+lm]=xa.x; sX[(lk+1)*64+lm]=xa.y; sX[(lk+2)*64+lm]=xa.z; sX[(lk+3)*64+lm]=xa.w;
        sX[(lk+4)*64+lm]=xb.x; sX[(lk+5)*64+lm]=xb.y; sX[(lk+6)*64+lm]=xb.z; sX[(lk+7)*64+lm]=xb.w;
        sW[(lk+0)*64+lm]=wa.x; sW[(lk+1)*64+lm]=wa.y; sW[(lk+2)*64+lm]=wa.z; sW[(lk+3)*64+lm]=wa.w;
        sW[(lk+4)*64+lm]=wb.x; sW[(lk+5)*64+lm]=wb.y; sW[(lk+6)*64+lm]=wb.z; sW[(lk+7)*64+lm]=wb.w;
        __syncthreads();
#pragma unroll
        for (int kk = 0; kk < 32; kk++) {
            float4 q = *(const float4*)(sX + kk * 64 + m0);
            u64 b0 = *(const u64*)(sW + kk * 64 + ac2);
            u64 b1 = *(const u64*)(sW + kk * 64 + ac2 + 32);
            u64 a;
            a = pk2(q.x,q.x); acc[0][0]=fma2(a,b0,acc[0][0]); acc[0][1]=fma2(a,b1,acc[0][1]);
            a = pk2(q.y,q.y); acc[1][0]=fma2(a,b0,acc[1][0]); acc[1][1]=fma2(a,b1,acc[1][1]);
            a = pk2(q.z,q.z); acc[2][0]=fma2(a,b0,acc[2][0]); acc[2][1]=fma2(a,b1,acc[2][1]);
            a = pk2(q.w,q.w); acc[3][0]=fma2(a,b0,acc[3][0]); acc[3][1]=fma2(a,b1,acc[3][1]);
        }
        __syncthreads();
    }
    const int c0 = col0 + ac2;
    const float b0 = bias[c0], b1 = bias[c0+1], b2 = bias[c0+32], b3 = bias[c0+33];
#pragma unroll
    for (int r = 0; r < 4; r++) {
        float x, y;
        upk2(acc[r][0], x, y);
        *(float2*)(out + (row0+m0+r)*HID + c0) = make_float2(x+b0, y+b1);
        upk2(acc[r][1], x, y);
        *(float2*)(out + (row0+m0+r)*HID + c0 + 32) = make_float2(x+b2, y+b3);
    }
}

// ---------------- fp32 -> bf16 hi/lo ----------------
__global__ __launch_bounds__(NTHREADS)
void convert_split_kernel(const float* __restrict__ x,
                          __nv_bfloat16* __restrict__ hi, __nv_bfloat16* __restrict__ lo)
{
    int i = (blockIdx.x * NTHREADS + threadIdx.x) * 4;
    float4 v = *(const float4*)(x + i);
    uint32_t hA, lA, hB, lB;
    split2(v.x, v.y, hA, lA);
    split2(v.z, v.w, hB, lB);
    *(uint2*)(hi + i) = make_uint2(hA, hB);
    *(uint2*)(lo + i) = make_uint2(lA, lB);
}

// ---------------- transpose V and split: g_vt*[hid][token] ----------------
__global__ __launch_bounds__(NTHREADS)
void vt_kernel(const float* __restrict__ v,
               __nv_bfloat16* __restrict__ vthi, __nv_bfloat16* __restrict__ vtlo)
{
    __shared__ float tile[64 * 64];
    const int j0 = blockIdx.x * 64, c0 = blockIdx.y * 64;
    const int tid = threadIdx.x;
    const int r = tid >> 4, c4 = (tid & 15) * 4;
#pragma unroll
    for (int i = 0; i < 4; i++)
        *(float4*)(tile + (r + 16*i) * 64 + c4) = *(const float4*)(v + (j0 + r + 16*i) * HID + c0 + c4);
    __syncthreads();
    const int n = tid >> 2, jb = (tid & 3) * 16;
    uint32_t h[8], l[8];
#pragma unroll
    for (int i = 0; i < 16; i += 2)
        split2(tile[(jb+i)*64 + n], tile[(jb+i+1)*64 + n], h[i>>1], l[i>>1]);
    size_t o = (size_t)(c0 + n) * NROWS + j0 + jb;
    *(uint4*)(vthi + o)     = make_uint4(h[0], h[1], h[2], h[3]);
    *(uint4*)(vthi + o + 8) = make_uint4(h[4], h[5], h[6], h[7]);
    *(uint4*)(vtlo + o)     = make_uint4(l[0], l[1], l[2], l[3]);
    *(uint4*)(vtlo + o + 8) = make_uint4(l[4], l[5], l[6], l[7]);
}

// ---------------- HMMA fused sigmoid attention ----------------
// Q/K tiles: 64 rows x 256 bf16, stride 528B. Vt tiles: 256 rows x 64 bf16,
// stride 144B. P tiles: 64 rows x 64 bf16, stride 144B. All strides give
// conflict-free ldmatrix (8 rows hit 8 distinct 16B bank groups).
#define STQ 528
#define STP 144
#define STV 144
#define QHI_O 0
#define QLO_O 33792
#define KHI_O 67584
#define KLO_O 101376
#define VTHI_O 135168
#define VTLO_O 172032
#define PHI_O 208896
#define PLO_O 218112
#define SMEMB 227328

__device__ __forceinline__ void stage64(char* smem, int off, const __nv_bfloat16* src,
                                        int r0, int tid) {
    for (int f = tid; f < 2048; f += NTHREADS) {
        int row = f >> 5, u = f & 31;
        *(uint4*)(smem + off + row * STQ + u * 16) =
            *(const uint4*)(src + (size_t)(r0 + row) * HID + u * 8);
    }
}
// stage Vt chunk: 256 rows x 64 bf16 (128B) from [hid][token] layout
__device__ __forceinline__ void stageVt(char* smem, int off, const __nv_bfloat16* src,
                                        int j0, int tid) {
    for (int f = tid; f < 2048; f += NTHREADS) {
        int row = f >> 3, u = f & 7;
        *(uint4*)(smem + off + row * STV + u * 16) =
            *(const uint4*)(src + (size_t)row * NROWS + j0 + u * 8);
    }
}

__global__ __launch_bounds__(NTHREADS)
void attn_kernel(float* __restrict__ out)
{
    extern __shared__ __align__(128) char smem[];
    const uint32_t sb = smem_to_u32(smem);
    const int tid = threadIdx.x, warp = tid >> 5, lane = tid & 31;
    const int mw = warp & 1;          // M half: rows 32*mw..
    const int nw = warp >> 1;         // N quarter
    const int row0 = blockIdx.x * 64;
    const int g = lane >> 3, rr = lane & 7;
    const int rr4 = lane >> 2, cc2 = (lane & 3) * 2;

    // ldmatrix lane offsets (bytes)
    const uint32_t loA_Q = (uint32_t)((rr + (g & 1) * 8) * STQ + (g >> 1) * 16);
    const uint32_t loA_P = (uint32_t)((rr + (g & 1) * 8) * STP + (g >> 1) * 16);
    const uint32_t loB_K = (uint32_t)((rr + (g >> 1) * 8) * STQ + (g & 1) * 16);
    const uint32_t loB_V = (uint32_t)((rr + (g >> 1) * 8) * STV + (g & 1) * 16);

    // stage Q hi/lo (resident for whole kernel)
    stage64(smem, QHI_O, g_qhi, row0, tid);
    stage64(smem, QLO_O, g_qlo, row0, tid);

    float oacc[2][8][4];
#pragma unroll
    for (int a = 0; a < 2; a++)
#pragma unroll
        for (int b = 0; b < 8; b++)
#pragma unroll
            for (int c = 0; c < 4; c++) oacc[a][b][c] = 0.0f;

    const uint32_t aQh = sb + QHI_O + (uint32_t)(mw * 32) * STQ + loA_Q;
    const uint32_t aQl = sb + QLO_O + (uint32_t)(mw * 32) * STQ + loA_Q;
    const uint32_t aPh = sb + PHI_O + (uint32_t)(mw * 32) * STP + loA_P;
    const uint32_t aPl = sb + PLO_O + (uint32_t)(mw * 32) * STP + loA_P;
    const uint32_t bK  = sb + (uint32_t)(nw * 16) * STQ + loB_K;   // + KHI_O/KLO_O
    const uint32_t bV  = sb + (uint32_t)(nw * 64) * STV + loB_V;   // + VTHI_O/VTLO_O

    for (int ch = 0; ch < NCHUNK; ch++) {
        const int j0 = ch * BJ;
        __syncthreads();                       // prev chunk done with K/V/P smem
        stage64(smem, KHI_O, g_khi, j0, tid);
        stage64(smem, KLO_O, g_klo, j0, tid);
        stageVt(smem, VTHI_O, g_vthi, j0, tid);
        stageVt(smem, VTLO_O, g_vtlo, j0, tid);
        __syncthreads();

        // ---- MMA1: S[64x64] = Q.K^T, 3-pass split ----
        float s[2][2][4];
#pragma unroll
        for (int a = 0; a < 2; a++)
#pragma unroll
            for (int b = 0; b < 2; b++)
#pragma unroll
                for (int c = 0; c < 4; c++) s[a][b][c] = 0.0f;

#pragma unroll 4
        for (int ks = 0; ks < 16; ks++) {
            const uint32_t ko = (uint32_t)(ks * 32);   // 16 bf16 = 32 bytes
            uint32_t ah0[4], ah1[4], al0[4], al1[4], bh[4], bl[4];
            ldsm4(ah0, aQh + ko);
            ldsm4(ah1, aQh + 16 * STQ + ko);
            ldsm4(al0, aQl + ko);
            ldsm4(al1, aQl + 16 * STQ + ko);
            ldsm4(bh, bK + KHI_O + ko);
            ldsm4(bl, bK + KLO_O + ko);
            mma16816(s[0][0], ah0, bh[0], bh[1]); mma16816(s[0][1], ah0, bh[2], bh[3]);
            mma16816(s[1][0], ah1, bh[0], bh[1]); mma16816(s[1][1], ah1, bh[2], bh[3]);
            mma16816(s[0][0], ah0, bl[0], bl[1]); mma16816(s[0][1], ah0, bl[2], bl[3]);
            mma16816(s[1][0], ah1, bl[0], bl[1]); mma16816(s[1][1], ah1, bl[2], bl[3]);
            mma16816(s[0][0], al0, bh[0], bh[1]); mma16816(s[0][1], al0, bh[2], bh[3]);
            mma16816(s[1][0], al1, bh[0], bh[1]); mma16816(s[1][1], al1, bh[2], bh[3]);
        }

        // ---- sigmoid + split -> P smem ----
#pragma unroll
        for (int mf = 0; mf < 2; mf++)
#pragma unroll
            for (int nf = 0; nf < 2; nf++) {
                const float* c = s[mf][nf];
                int m = mw * 32 + mf * 16 + rr4;
                int n = nw * 16 + nf * 8 + cc2;
                uint32_t h, l;
                split2(fsig(c[0]), fsig(c[1]), h, l);
                *(uint32_t*)(smem + PHI_O + m * STP + n * 2) = h;
                *(uint32_t*)(smem + PLO_O + m * STP + n * 2) = l;
                split2(fsig(c[2]), fsig(c[3]), h, l);
                *(uint32_t*)(smem + PHI_O + (m + 8) * STP + n * 2) = h;
                *(uint32_t*)(smem + PLO_O + (m + 8) * STP + n * 2) = l;
            }
        __syncthreads();

        // ---- MMA2: O[64x256] += P.V (B = Vt[hid][j]), 3-pass split ----
#pragma unroll
        for (int ks = 0; ks < 4; ks++) {
            const uint32_t ko = (uint32_t)(ks * 32);   // 16 j = 32 bytes
            uint32_t ph0[4], ph1[4], pl0[4], pl1[4];
            ldsm4(ph0, aPh + ko);
            ldsm4(ph1, aPh + 16 * STP + ko);
            ldsm4(pl0, aPl + ko);
            ldsm4(pl1, aPl + 16 * STP + ko);
#pragma unroll
            for (int t = 0; t < 4; t++) {
                uint32_t bh[4], bl[4];
                ldsm4(bh, bV + VTHI_O + (uint32_t)(t * 16) * STV + ko);
                ldsm4(bl, bV + VTLO_O + (uint32_t)(t * 16) * STV + ko);
                float* o00 = oacc[0][t * 2]; float* o01 = oacc[0][t * 2 + 1];
                float* o10 = oacc[1][t * 2]; float* o11 = oacc[1][t * 2 + 1];
                mma16816(o00, ph0, bh[0], bh[1]); mma16816(o01, ph0, bh[2], bh[3]);
                mma16816(o10, ph1, bh[0], bh[1]); mma16816(o11, ph1, bh[2], bh[3]);
                mma16816(o00, ph0, bl[0], bl[1]); mma16816(o01, ph0, bl[2], bl[3]);
                mma16816(o10, ph1, bl[0], bl[1]); mma16816(o11, ph1, bl[2], bl[3]);
                mma16816(o00, pl0, bh[0], bh[1]); mma16816(o01, pl0, bh[2], bh[3]);
                mma16816(o10, pl1, bh[0], bh[1]); mma16816(o11, pl1, bh[2], bh[3]);
            }
        }
    }

    // ---- epilogue ----
#pragma unroll
    for (int mf = 0; mf < 2; mf++)
#pragma unroll
        for (int j = 0; j < 8; j++) {
            const float* c = oacc[mf][j];
            int m = row0 + mw * 32 + mf * 16 + rr4;
            int col = nw * 64 + (j >> 1) * 16 + (j & 1) * 8 + cc2;
            *(float2*)(out + (size_t)m * HID + col) = make_float2(c[0], c[1]);
            *(float2*)(out + (size_t)(m + 8) * HID + col) = make_float2(c[2], c[3]);
        }
}

// ---------------------------------------------------------------------------
extern "C" void kernel_launch(void* const* d_in, const int* in_sizes, int n_in,
                              void* d_out, int out_size)
{
    const float* query = (const float*)d_in[0];
    const float* key_  = (const float*)d_in[1];
    const float* value = (const float*)d_in[2];
    const float* Wq = (const float*)d_in[3];
    const float* bq = (const float*)d_in[4];
    const float* Wk = (const float*)d_in[5];
    const float* bk = (const float*)d_in[6];
    const float* Wv = (const float*)d_in[7];
    const float* bv = (const float*)d_in[8];
    float* out = (float*)d_out;
    (void)in_sizes; (void)n_in; (void)out_size;

    float *dq, *dk, *dv;
    __nv_bfloat16 *qh, *ql, *kh, *kl, *vth, *vtl;
    cudaGetSymbolAddress((void**)&dq, g_q);
    cudaGetSymbolAddress((void**)&dk, g_k);
    cudaGetSymbolAddress((void**)&dv, g_v);
    cudaGetSymbolAddress((void**)&qh, g_qhi);
    cudaGetSymbolAddress((void**)&ql, g_qlo);
    cudaGetSymbolAddress((void**)&kh, g_khi);
    cudaGetSymbolAddress((void**)&kl, g_klo);
    cudaGetSymbolAddress((void**)&vth, g_vthi);
    cudaGetSymbolAddress((void**)&vtl, g_vtlo);

    dim3 lgrid(NROWS / 64, HID / 64);
    linear_kernel<<<lgrid, NTHREADS>>>(query, Wq, bq, dq);
    linear_kernel<<<lgrid, NTHREADS>>>(key_,  Wk, bk, dk);
    linear_kernel<<<lgrid, NTHREADS>>>(value, Wv, bv, dv);

    int cgrid = NROWS * HID / 4 / NTHREADS;   // 2048
    convert_split_kernel<<<cgrid, NTHREADS>>>(dq, qh, ql);
    convert_split_kernel<<<cgrid, NTHREADS>>>(dk, kh, kl);
    vt_kernel<<<dim3(NROWS / 64, HID / 64), NTHREADS>>>(dv, vth, vtl);

    cudaFuncSetAttribute(attn_kernel, cudaFuncAttributeMaxDynamicSharedMemorySize, SMEMB);
    attn_kernel<<<NROWS / 64, NTHREADS, SMEMB>>>(out);
}

// round 6
// speedup vs baseline: 3.1914x; 1.4373x over previous
#include <cuda_runtime.h>
#include <cuda_bf16.h>
#include <cuda_fp16.h>
#include <cstdint>

#define NROWS 8192
#define HID   256
#define NTHREADS 256
#define BJ 64
#define NCHUNK (NROWS / BJ)

// ---------------- device scratch ----------------
__device__ float g_v[NROWS * HID];
__device__ __nv_bfloat16 g_qhi[NROWS * HID], g_qlo[NROWS * HID];
__device__ __nv_bfloat16 g_khi[NROWS * HID], g_klo[NROWS * HID];
__device__ __half g_vtf[HID * NROWS];   // [hid][token] fp16

typedef unsigned long long u64;
__device__ __forceinline__ u64 pk2(float x, float y) {
    u64 r; asm("mov.b64 %0, {%1,%2};" : "=l"(r) : "f"(x), "f"(y)); return r;
}
__device__ __forceinline__ void upk2(u64 v, float& x, float& y) {
    asm("mov.b64 {%0,%1}, %2;" : "=f"(x), "=f"(y) : "l"(v));
}
__device__ __forceinline__ u64 fma2(u64 a, u64 b, u64 c) {
    u64 d; asm("fma.rn.f32x2 %0, %1, %2, %3;" : "=l"(d) : "l"(a), "l"(b), "l"(c)); return d;
}
__device__ __forceinline__ float fsig(float x) {
    return __frcp_rn(1.0f + __expf(-x));
}
__device__ __forceinline__ void split2(float a, float b, uint32_t& hi, uint32_t& lo) {
    __nv_bfloat16 ha = __float2bfloat16(a), hb = __float2bfloat16(b);
    float ra = a - __bfloat162float(ha), rb = b - __bfloat162float(hb);
    hi = ((uint32_t)__bfloat16_as_ushort(hb) << 16) | (uint32_t)__bfloat16_as_ushort(ha);
    __nv_bfloat16 la = __float2bfloat16(ra), lb = __float2bfloat16(rb);
    lo = ((uint32_t)__bfloat16_as_ushort(lb) << 16) | (uint32_t)__bfloat16_as_ushort(la);
}
__device__ __forceinline__ uint32_t h2pack(float a, float b) {
    __half2 h = __floats2half2_rn(a, b);
    return *(uint32_t*)&h;
}
__device__ __forceinline__ uint32_t smem_to_u32(const void* p) {
    uint32_t a;
    asm("{ .reg .u64 t; cvta.to.shared.u64 t, %1; cvt.u32.u64 %0, t; }" : "=r"(a) : "l"(p));
    return a;
}
__device__ __forceinline__ void ldsm4(uint32_t r[4], uint32_t addr) {
    asm volatile("ldmatrix.sync.aligned.m8n8.x4.shared.b16 {%0,%1,%2,%3}, [%4];"
                 : "=r"(r[0]), "=r"(r[1]), "=r"(r[2]), "=r"(r[3]) : "r"(addr));
}
__device__ __forceinline__ void mma_bf16(float c[4], const uint32_t a[4], uint32_t b0, uint32_t b1) {
    asm volatile("mma.sync.aligned.m16n8k16.row.col.f32.bf16.bf16.f32 "
                 "{%0,%1,%2,%3}, {%4,%5,%6,%7}, {%8,%9}, {%0,%1,%2,%3};"
                 : "+f"(c[0]), "+f"(c[1]), "+f"(c[2]), "+f"(c[3])
                 : "r"(a[0]), "r"(a[1]), "r"(a[2]), "r"(a[3]), "r"(b0), "r"(b1));
}
__device__ __forceinline__ void mma_f16(float c[4], const uint32_t a[4], uint32_t b0, uint32_t b1) {
    asm volatile("mma.sync.aligned.m16n8k16.row.col.f32.f16.f16.f32 "
                 "{%0,%1,%2,%3}, {%4,%5,%6,%7}, {%8,%9}, {%0,%1,%2,%3};"
                 : "+f"(c[0]), "+f"(c[1]), "+f"(c[2]), "+f"(c[3])
                 : "r"(a[0]), "r"(a[1]), "r"(a[2]), "r"(a[3]), "r"(b0), "r"(b1));
}
__device__ __forceinline__ void cpasync16(uint32_t saddr, const void* g) {
    asm volatile("cp.async.cg.shared.global [%0], [%1], 16;" :: "r"(saddr), "l"(g));
}
#define CP_COMMIT() asm volatile("cp.async.commit_group;" ::: "memory")
#define CP_WAIT0()  asm volatile("cp.async.wait_group 0;" ::: "memory")

// ---------------- fp32 linear core (proven) ----------------
// EPI = 0: write fp32 out ; EPI = 1: write bf16 hi/lo split
template <int EPI>
__device__ __forceinline__ void linear_body(const float* __restrict__ X, const float* __restrict__ W,
                                            const float* __restrict__ bias, float* __restrict__ out,
                                            __nv_bfloat16* __restrict__ ohi, __nv_bfloat16* __restrict__ olo)
{
    __shared__ float sX[32 * 64];
    __shared__ float sW[32 * 64];
    const int tid = threadIdx.x;
    const int row0 = blockIdx.x * 64, col0 = blockIdx.y * 64;
    const int m0 = (tid >> 4) << 2, ac2 = (tid & 15) << 1;
    const int lm = tid & 63, lk = (tid >> 6) << 3;
    u64 acc[4][2];
#pragma unroll
    for (int r = 0; r < 4; r++) { acc[r][0] = 0ull; acc[r][1] = 0ull; }
    const float* Xp = X + (row0 + lm) * HID + lk;
    const float* Wp = W + (col0 + lm) * HID + lk;
    for (int k0 = 0; k0 < HID; k0 += 32) {
        float4 xa = *(const float4*)(Xp + k0), xb = *(const float4*)(Xp + k0 + 4);
        float4 wa = *(const float4*)(Wp + k0), wb = *(const float4*)(Wp + k0 + 4);
        sX[(lk+0)*64+lm]=xa.x; sX[(lk+1)*64+lm]=xa.y; sX[(lk+2)*64+lm]=xa.z; sX[(lk+3)*64+lm]=xa.w;
        sX[(lk+4)*64+lm]=xb.x; sX[(lk+5)*64+lm]=xb.y; sX[(lk+6)*64+lm]=xb.z; sX[(lk+7)*64+lm]=xb.w;
        sW[(lk+0)*64+lm]=wa.x; sW[(lk+1)*64+lm]=wa.y; sW[(lk+2)*64+lm]=wa.z; sW[(lk+3)*64+lm]=wa.w;
        sW[(lk+4)*64+lm]=wb.x; sW[(lk+5)*64+lm]=wb.y; sW[(lk+6)*64+lm]=wb.z; sW[(lk+7)*64+lm]=wb.w;
        __syncthreads();
#pragma unroll
        for (int kk = 0; kk < 32; kk++) {
            float4 q = *(const float4*)(sX + kk * 64 + m0);
            u64 b0 = *(const u64*)(sW + kk * 64 + ac2);
            u64 b1 = *(const u64*)(sW + kk * 64 + ac2 + 32);
            u64 a;
            a = pk2(q.x,q.x); acc[0][0]=fma2(a,b0,acc[0][0]); acc[0][1]=fma2(a,b1,acc[0][1]);
            a = pk2(q.y,q.y); acc[1][0]=fma2(a,b0,acc[1][0]); acc[1][1]=fma2(a,b1,acc[1][1]);
            a = pk2(q.z,q.z); acc[2][0]=fma2(a,b0,acc[2][0]); acc[2][1]=fma2(a,b1,acc[2][1]);
            a = pk2(q.w,q.w); acc[3][0]=fma2(a,b0,acc[3][0]); acc[3][1]=fma2(a,b1,acc[3][1]);
        }
        __syncthreads();
    }
    const int c0 = col0 + ac2;
    const float b0 = bias[c0], b1 = bias[c0+1], b2 = bias[c0+32], b3 = bias[c0+33];
#pragma unroll
    for (int r = 0; r < 4; r++) {
        float x, y;
        size_t ro = (size_t)(row0 + m0 + r) * HID;
        upk2(acc[r][0], x, y);
        if (EPI == 0) {
            *(float2*)(out + ro + c0) = make_float2(x + b0, y + b1);
        } else {
            uint32_t h, l; split2(x + b0, y + b1, h, l);
            *(uint32_t*)(ohi + ro + c0) = h;
            *(uint32_t*)(olo + ro + c0) = l;
        }
        upk2(acc[r][1], x, y);
        if (EPI == 0) {
            *(float2*)(out + ro + c0 + 32) = make_float2(x + b2, y + b3);
        } else {
            uint32_t h, l; split2(x + b2, y + b3, h, l);
            *(uint32_t*)(ohi + ro + c0 + 32) = h;
            *(uint32_t*)(olo + ro + c0 + 32) = l;
        }
    }
}

__global__ __launch_bounds__(NTHREADS)
void linear_f32_kernel(const float* __restrict__ X, const float* __restrict__ W,
                       const float* __restrict__ bias, float* __restrict__ out)
{ linear_body<0>(X, W, bias, out, nullptr, nullptr); }

__global__ __launch_bounds__(NTHREADS)
void linear_split_kernel(const float* __restrict__ X, const float* __restrict__ W,
                         const float* __restrict__ bias,
                         __nv_bfloat16* __restrict__ ohi, __nv_bfloat16* __restrict__ olo)
{ linear_body<1>(X, W, bias, nullptr, ohi, olo); }

// ---------------- transpose V -> fp16 [hid][token] ----------------
__global__ __launch_bounds__(NTHREADS)
void vt_kernel(const float* __restrict__ v, __half* __restrict__ vtf)
{
    __shared__ float tile[64 * 64];
    const int j0 = blockIdx.x * 64, c0 = blockIdx.y * 64;
    const int tid = threadIdx.x;
    const int r = tid >> 4, c4 = (tid & 15) * 4;
#pragma unroll
    for (int i = 0; i < 4; i++)
        *(float4*)(tile + (r + 16*i) * 64 + c4) = *(const float4*)(v + (j0 + r + 16*i) * HID + c0 + c4);
    __syncthreads();
    const int n = tid >> 2, jb = (tid & 3) * 16;
    uint32_t h[8];
#pragma unroll
    for (int i = 0; i < 16; i += 2)
        h[i >> 1] = h2pack(tile[(jb+i)*64 + n], tile[(jb+i+1)*64 + n]);
    size_t o = (size_t)(c0 + n) * NROWS + j0 + jb;
    *(uint4*)(vtf + o)     = make_uint4(h[0], h[1], h[2], h[3]);
    *(uint4*)(vtf + o + 8) = make_uint4(h[4], h[5], h[6], h[7]);
}

// ---------------- HMMA fused sigmoid attention ----------------
// Q/K tiles 64x256 bf16 stride 528B; Vt tile 256x64 fp16 stride 144B;
// P tile 64x64 fp16 stride 144B. Strides keep ldmatrix conflict-free.
#define STQ 528
#define STP 144
#define STV 144
#define QHI_O 0
#define QLO_O 33792
#define KHI_O 67584
#define KLO_O 101376
#define VT_O  135168
#define P_O   172032
#define SMEMB 181248

__device__ __forceinline__ void stage64_async(uint32_t sb, int off, const __nv_bfloat16* src,
                                              int r0, int tid) {
    for (int f = tid; f < 2048; f += NTHREADS) {
        int row = f >> 5, u = f & 31;
        cpasync16(sb + off + row * STQ + u * 16, src + (size_t)(r0 + row) * HID + u * 8);
    }
}
__device__ __forceinline__ void stageVt_async(uint32_t sb, int off, const __half* src,
                                              int j0, int tid) {
    for (int f = tid; f < 2048; f += NTHREADS) {
        int row = f >> 3, u = f & 7;
        cpasync16(sb + off + row * STV + u * 16, src + (size_t)row * NROWS + j0 + u * 8);
    }
}

__global__ __launch_bounds__(NTHREADS)
void attn_kernel(float* __restrict__ out)
{
    extern __shared__ __align__(128) char smem[];
    const uint32_t sb = smem_to_u32(smem);
    const int tid = threadIdx.x, warp = tid >> 5, lane = tid & 31;
    const int mw = warp & 1;          // M half
    const int nw = warp >> 1;         // N quarter
    const int row0 = blockIdx.x * 64;
    const int g = lane >> 3, rr = lane & 7;
    const int rr4 = lane >> 2, cc2 = (lane & 3) * 2;

    const uint32_t loA_Q = (uint32_t)((rr + (g & 1) * 8) * STQ + (g >> 1) * 16);
    const uint32_t loA_P = (uint32_t)((rr + (g & 1) * 8) * STP + (g >> 1) * 16);
    const uint32_t loB_K = (uint32_t)((rr + (g >> 1) * 8) * STQ + (g & 1) * 16);
    const uint32_t loB_V = (uint32_t)((rr + (g >> 1) * 8) * STV + (g & 1) * 16);

    // stage resident Q hi/lo
    stage64_async(sb, QHI_O, g_qhi, row0, tid);
    stage64_async(sb, QLO_O, g_qlo, row0, tid);
    CP_COMMIT();

    float oacc[2][8][4];
#pragma unroll
    for (int a = 0; a < 2; a++)
#pragma unroll
        for (int b = 0; b < 8; b++)
#pragma unroll
            for (int c = 0; c < 4; c++) oacc[a][b][c] = 0.0f;

    const uint32_t aQh = sb + QHI_O + (uint32_t)(mw * 32) * STQ + loA_Q;
    const uint32_t aQl = sb + QLO_O + (uint32_t)(mw * 32) * STQ + loA_Q;
    const uint32_t aP  = sb + P_O   + (uint32_t)(mw * 32) * STP + loA_P;
    const uint32_t bK  = sb + (uint32_t)(nw * 16) * STQ + loB_K;   // + KHI_O/KLO_O
    const uint32_t bV  = sb + VT_O + (uint32_t)(nw * 64) * STV + loB_V;

    for (int ch = 0; ch < NCHUNK; ch++) {
        const int j0 = ch * BJ;
        __syncthreads();                       // prev chunk done with K/V/P smem
        stage64_async(sb, KHI_O, g_khi, j0, tid);
        stage64_async(sb, KLO_O, g_klo, j0, tid);
        stageVt_async(sb, VT_O, g_vtf, j0, tid);
        CP_COMMIT();
        CP_WAIT0();
        __syncthreads();

        // ---- MMA1: S[64x64] = Q.K^T, 3-pass bf16 split ----
        float s[2][2][4];
#pragma unroll
        for (int a = 0; a < 2; a++)
#pragma unroll
            for (int b = 0; b < 2; b++)
#pragma unroll
                for (int c = 0; c < 4; c++) s[a][b][c] = 0.0f;

#pragma unroll 4
        for (int ks = 0; ks < 16; ks++) {
            const uint32_t ko = (uint32_t)(ks * 32);
            uint32_t ah0[4], ah1[4], al0[4], al1[4], bh[4], bl[4];
            ldsm4(ah0, aQh + ko);
            ldsm4(ah1, aQh + 16 * STQ + ko);
            ldsm4(al0, aQl + ko);
            ldsm4(al1, aQl + 16 * STQ + ko);
            ldsm4(bh, bK + KHI_O + ko);
            ldsm4(bl, bK + KLO_O + ko);
            mma_bf16(s[0][0], ah0, bh[0], bh[1]); mma_bf16(s[0][1], ah0, bh[2], bh[3]);
            mma_bf16(s[1][0], ah1, bh[0], bh[1]); mma_bf16(s[1][1], ah1, bh[2], bh[3]);
            mma_bf16(s[0][0], ah0, bl[0], bl[1]); mma_bf16(s[0][1], ah0, bl[2], bl[3]);
            mma_bf16(s[1][0], ah1, bl[0], bl[1]); mma_bf16(s[1][1], ah1, bl[2], bl[3]);
            mma_bf16(s[0][0], al0, bh[0], bh[1]); mma_bf16(s[0][1], al0, bh[2], bh[3]);
            mma_bf16(s[1][0], al1, bh[0], bh[1]); mma_bf16(s[1][1], al1, bh[2], bh[3]);
        }

        // ---- sigmoid -> fp16 P smem ----
#pragma unroll
        for (int mf = 0; mf < 2; mf++)
#pragma unroll
            for (int nf = 0; nf < 2; nf++) {
                const float* c = s[mf][nf];
                int m = mw * 32 + mf * 16 + rr4;
                int n = nw * 16 + nf * 8 + cc2;
                *(uint32_t*)(smem + P_O + m * STP + n * 2) = h2pack(fsig(c[0]), fsig(c[1]));
                *(uint32_t*)(smem + P_O + (m + 8) * STP + n * 2) = h2pack(fsig(c[2]), fsig(c[3]));
            }
        __syncthreads();

        // ---- MMA2: O[64x256] += P.V, single-pass fp16 ----
#pragma unroll
        for (int ks = 0; ks < 4; ks++) {
            const uint32_t ko = (uint32_t)(ks * 32);
            uint32_t p0[4], p1[4];
            ldsm4(p0, aP + ko);
            ldsm4(p1, aP + 16 * STP + ko);
#pragma unroll
            for (int t = 0; t < 4; t++) {
                uint32_t bh[4];
                ldsm4(bh, bV + (uint32_t)(t * 16) * STV + ko);
                mma_f16(oacc[0][t * 2], p0, bh[0], bh[1]);
                mma_f16(oacc[0][t * 2 + 1], p0, bh[2], bh[3]);
                mma_f16(oacc[1][t * 2], p1, bh[0], bh[1]);
                mma_f16(oacc[1][t * 2 + 1], p1, bh[2], bh[3]);
            }
        }
    }

    // ---- epilogue ----
#pragma unroll
    for (int mf = 0; mf < 2; mf++)
#pragma unroll
        for (int j = 0; j < 8; j++) {
            const float* c = oacc[mf][j];
            int m = row0 + mw * 32 + mf * 16 + rr4;
            int col = nw * 64 + (j >> 1) * 16 + (j & 1) * 8 + cc2;
            *(float2*)(out + (size_t)m * HID + col) = make_float2(c[0], c[1]);
            *(float2*)(out + (size_t)(m + 8) * HID + col) = make_float2(c[2], c[3]);
        }
}

// ---------------------------------------------------------------------------
extern "C" void kernel_launch(void* const* d_in, const int* in_sizes, int n_in,
                              void* d_out, int out_size)
{
    const float* query = (const float*)d_in[0];
    const float* key_  = (const float*)d_in[1];
    const float* value = (const float*)d_in[2];
    const float* Wq = (const float*)d_in[3];
    const float* bq = (const float*)d_in[4];
    const float* Wk = (const float*)d_in[5];
    const float* bk = (const float*)d_in[6];
    const float* Wv = (const float*)d_in[7];
    const float* bv = (const float*)d_in[8];
    float* out = (float*)d_out;
    (void)in_sizes; (void)n_in; (void)out_size;

    float* dv;
    __nv_bfloat16 *qh, *ql, *kh, *kl;
    __half* vtf;
    cudaGetSymbolAddress((void**)&dv, g_v);
    cudaGetSymbolAddress((void**)&qh, g_qhi);
    cudaGetSymbolAddress((void**)&ql, g_qlo);
    cudaGetSymbolAddress((void**)&kh, g_khi);
    cudaGetSymbolAddress((void**)&kl, g_klo);
    cudaGetSymbolAddress((void**)&vtf, g_vtf);

    dim3 lgrid(NROWS / 64, HID / 64);
    linear_split_kernel<<<lgrid, NTHREADS>>>(query, Wq, bq, qh, ql);
    linear_split_kernel<<<lgrid, NTHREADS>>>(key_,  Wk, bk, kh, kl);
    linear_f32_kernel<<<lgrid, NTHREADS>>>(value, Wv, bv, dv);
    vt_kernel<<<dim3(NROWS / 64, HID / 64), NTHREADS>>>(dv, vtf);

    cudaFuncSetAttribute(attn_kernel, cudaFuncAttributeMaxDynamicSharedMemorySize, SMEMB);
    attn_kernel<<<NROWS / 64, NTHREADS, SMEMB>>>(out);
}

// round 7
// speedup vs baseline: 5.6170x; 1.7601x over previous
#include <cuda_runtime.h>
#include <cuda_bf16.h>
#include <cuda_fp16.h>
#include <cstdint>

#define NROWS 8192
#define HID   256
#define NTHREADS 256
#define BJ 64
#define NCHUNK (NROWS / BJ)

// ---------------- device scratch ----------------
__device__ float g_v[NROWS * HID];
__device__ __half g_qf[NROWS * HID];
__device__ __half g_kf[NROWS * HID];
__device__ __half g_vtf[HID * NROWS];   // [hid][token] fp16

typedef unsigned long long u64;
__device__ __forceinline__ u64 pk2(float x, float y) {
    u64 r; asm("mov.b64 %0, {%1,%2};" : "=l"(r) : "f"(x), "f"(y)); return r;
}
__device__ __forceinline__ void upk2(u64 v, float& x, float& y) {
    asm("mov.b64 {%0,%1}, %2;" : "=f"(x), "=f"(y) : "l"(v));
}
__device__ __forceinline__ u64 fma2(u64 a, u64 b, u64 c) {
    u64 d; asm("fma.rn.f32x2 %0, %1, %2, %3;" : "=l"(d) : "l"(a), "l"(b), "l"(c)); return d;
}
// sigmoid via HW tanh: sigma(x) = 0.5*tanh(x/2) + 0.5
__device__ __forceinline__ float fsig(float x) {
    float t; asm("tanh.approx.f32 %0, %1;" : "=f"(t) : "f"(x * 0.5f));
    return fmaf(0.5f, t, 0.5f);
}
__device__ __forceinline__ uint32_t h2pack(float a, float b) {
    __half2 h = __floats2half2_rn(a, b);
    return *(uint32_t*)&h;
}
__device__ __forceinline__ uint32_t smem_to_u32(const void* p) {
    uint32_t a;
    asm("{ .reg .u64 t; cvta.to.shared.u64 t, %1; cvt.u32.u64 %0, t; }" : "=r"(a) : "l"(p));
    return a;
}
__device__ __forceinline__ void ldsm4(uint32_t r[4], uint32_t addr) {
    asm volatile("ldmatrix.sync.aligned.m8n8.x4.shared.b16 {%0,%1,%2,%3}, [%4];"
                 : "=r"(r[0]), "=r"(r[1]), "=r"(r[2]), "=r"(r[3]) : "r"(addr));
}
__device__ __forceinline__ void mma_f16(float c[4], const uint32_t a[4], uint32_t b0, uint32_t b1) {
    asm volatile("mma.sync.aligned.m16n8k16.row.col.f32.f16.f16.f32 "
                 "{%0,%1,%2,%3}, {%4,%5,%6,%7}, {%8,%9}, {%0,%1,%2,%3};"
                 : "+f"(c[0]), "+f"(c[1]), "+f"(c[2]), "+f"(c[3])
                 : "r"(a[0]), "r"(a[1]), "r"(a[2]), "r"(a[3]), "r"(b0), "r"(b1));
}
__device__ __forceinline__ void cpasync16(uint32_t saddr, const void* g) {
    asm volatile("cp.async.cg.shared.global [%0], [%1], 16;" :: "r"(saddr), "l"(g));
}
#define CP_COMMIT() asm volatile("cp.async.commit_group;" ::: "memory")
#define CP_WAIT(N)  asm volatile("cp.async.wait_group %0;" :: "n"(N) : "memory")

// ---------------- fp32 linear core (proven) ----------------
// EPI=0: fp32 out ; EPI=1: fp16 out
template <int EPI>
__device__ __forceinline__ void linear_body(const float* __restrict__ X, const float* __restrict__ W,
                                            const float* __restrict__ bias, float* __restrict__ out,
                                            __half* __restrict__ of16)
{
    __shared__ float sX[32 * 64];
    __shared__ float sW[32 * 64];
    const int tid = threadIdx.x;
    const int row0 = blockIdx.x * 64, col0 = blockIdx.y * 64;
    const int m0 = (tid >> 4) << 2, ac2 = (tid & 15) << 1;
    const int lm = tid & 63, lk = (tid >> 6) << 3;
    u64 acc[4][2];
#pragma unroll
    for (int r = 0; r < 4; r++) { acc[r][0] = 0ull; acc[r][1] = 0ull; }
    const float* Xp = X + (row0 + lm) * HID + lk;
    const float* Wp = W + (col0 + lm) * HID + lk;
    for (int k0 = 0; k0 < HID; k0 += 32) {
        float4 xa = *(const float4*)(Xp + k0), xb = *(const float4*)(Xp + k0 + 4);
        float4 wa = *(const float4*)(Wp + k0), wb = *(const float4*)(Wp + k0 + 4);
        sX[(lk+0)*64+lm]=xa.x; sX[(lk+1)*64+lm]=xa.y; sX[(lk+2)*64+lm]=xa.z; sX[(lk+3)*64+lm]=xa.w;
        sX[(lk+4)*64+lm]=xb.x; sX[(lk+5)*64+lm]=xb.y; sX[(lk+6)*64+lm]=xb.z; sX[(lk+7)*64+lm]=xb.w;
        sW[(lk+0)*64+lm]=wa.x; sW[(lk+1)*64+lm]=wa.y; sW[(lk+2)*64+lm]=wa.z; sW[(lk+3)*64+lm]=wa.w;
        sW[(lk+4)*64+lm]=wb.x; sW[(lk+5)*64+lm]=wb.y; sW[(lk+6)*64+lm]=wb.z; sW[(lk+7)*64+lm]=wb.w;
        __syncthreads();
#pragma unroll
        for (int kk = 0; kk < 32; kk++) {
            float4 q = *(const float4*)(sX + kk * 64 + m0);
            u64 b0 = *(const u64*)(sW + kk * 64 + ac2);
            u64 b1 = *(const u64*)(sW + kk * 64 + ac2 + 32);
            u64 a;
            a = pk2(q.x,q.x); acc[0][0]=fma2(a,b0,acc[0][0]); acc[0][1]=fma2(a,b1,acc[0][1]);
            a = pk2(q.y,q.y); acc[1][0]=fma2(a,b0,acc[1][0]); acc[1][1]=fma2(a,b1,acc[1][1]);
            a = pk2(q.z,q.z); acc[2][0]=fma2(a,b0,acc[2][0]); acc[2][1]=fma2(a,b1,acc[2][1]);
            a = pk2(q.w,q.w); acc[3][0]=fma2(a,b0,acc[3][0]); acc[3][1]=fma2(a,b1,acc[3][1]);
        }
        __syncthreads();
    }
    const int c0 = col0 + ac2;
    const float b0 = bias[c0], b1 = bias[c0+1], b2 = bias[c0+32], b3 = bias[c0+33];
#pragma unroll
    for (int r = 0; r < 4; r++) {
        float x, y;
        size_t ro = (size_t)(row0 + m0 + r) * HID;
        upk2(acc[r][0], x, y);
        if (EPI == 0) *(float2*)(out + ro + c0) = make_float2(x + b0, y + b1);
        else          *(uint32_t*)(of16 + ro + c0) = h2pack(x + b0, y + b1);
        upk2(acc[r][1], x, y);
        if (EPI == 0) *(float2*)(out + ro + c0 + 32) = make_float2(x + b2, y + b3);
        else          *(uint32_t*)(of16 + ro + c0 + 32) = h2pack(x + b2, y + b3);
    }
}

__global__ __launch_bounds__(NTHREADS)
void linear_f32_kernel(const float* __restrict__ X, const float* __restrict__ W,
                       const float* __restrict__ bias, float* __restrict__ out)
{ linear_body<0>(X, W, bias, out, nullptr); }

__global__ __launch_bounds__(NTHREADS)
void linear_f16_kernel(const float* __restrict__ X, const float* __restrict__ W,
                       const float* __restrict__ bias, __half* __restrict__ of16)
{ linear_body<1>(X, W, bias, nullptr, of16); }

// ---------------- transpose V -> fp16 [hid][token] ----------------
__global__ __launch_bounds__(NTHREADS)
void vt_kernel(const float* __restrict__ v, __half* __restrict__ vtf)
{
    __shared__ float tile[64 * 64];
    const int j0 = blockIdx.x * 64, c0 = blockIdx.y * 64;
    const int tid = threadIdx.x;
    const int r = tid >> 4, c4 = (tid & 15) * 4;
#pragma unroll
    for (int i = 0; i < 4; i++)
        *(float4*)(tile + (r + 16*i) * 64 + c4) = *(const float4*)(v + (j0 + r + 16*i) * HID + c0 + c4);
    __syncthreads();
    const int n = tid >> 2, jb = (tid & 3) * 16;
    uint32_t h[8];
#pragma unroll
    for (int i = 0; i < 16; i += 2)
        h[i >> 1] = h2pack(tile[(jb+i)*64 + n], tile[(jb+i+1)*64 + n]);
    size_t o = (size_t)(c0 + n) * NROWS + j0 + jb;
    *(uint4*)(vtf + o)     = make_uint4(h[0], h[1], h[2], h[3]);
    *(uint4*)(vtf + o + 8) = make_uint4(h[4], h[5], h[6], h[7]);
}

// ---------------- HMMA fused sigmoid attention (all fp16, double-buffered) --
// Q tile 64x256 fp16 stride 528B; K tile 64x256 stride 528B; Vt tile 256x64
// stride 144B; P tile 64x64 stride 144B. Strides keep ldmatrix conflict-free.
#define STQ 528
#define STP 144
#define STV 144
#define Q_O    0
#define K_O    33792           // buffer 0; buffer 1 at +BUFSZ
#define V_O    67584
#define BUFSZ  70656           // K (33792) + Vt (36864)
#define P_O    175104
#define SMEMB  184320

__device__ __forceinline__ void stageK_async(uint32_t sb, int off, const __half* src,
                                             int r0, int tid) {
    for (int f = tid; f < 2048; f += NTHREADS) {
        int row = f >> 5, u = f & 31;
        cpasync16(sb + off + row * STQ + u * 16, src + (size_t)(r0 + row) * HID + u * 8);
    }
}
__device__ __forceinline__ void stageVt_async(uint32_t sb, int off, const __half* src,
                                              int j0, int tid) {
    for (int f = tid; f < 2048; f += NTHREADS) {
        int row = f >> 3, u = f & 7;
        cpasync16(sb + off + row * STV + u * 16, src + (size_t)row * NROWS + j0 + u * 8);
    }
}

__global__ __launch_bounds__(NTHREADS)
void attn_kernel(float* __restrict__ out)
{
    extern __shared__ __align__(128) char smem[];
    const uint32_t sb = smem_to_u32(smem);
    const int tid = threadIdx.x, warp = tid >> 5, lane = tid & 31;
    const int mw = warp & 1;          // M half
    const int nw = warp >> 1;         // N quarter
    const int row0 = blockIdx.x * 64;
    const int g = lane >> 3, rr = lane & 7;
    const int rr4 = lane >> 2, cc2 = (lane & 3) * 2;

    const uint32_t loA_Q = (uint32_t)((rr + (g & 1) * 8) * STQ + (g >> 1) * 16);
    const uint32_t loA_P = (uint32_t)((rr + (g & 1) * 8) * STP + (g >> 1) * 16);
    const uint32_t loB_K = (uint32_t)((rr + (g >> 1) * 8) * STQ + (g & 1) * 16);
    const uint32_t loB_V = (uint32_t)((rr + (g >> 1) * 8) * STV + (g & 1) * 16);

    // stage resident Q, then first K/Vt chunk into buffer 0
    stageK_async(sb, Q_O, g_qf, row0, tid);
    stageK_async(sb, K_O, g_kf, 0, tid);
    stageVt_async(sb, V_O, g_vtf, 0, tid);
    CP_COMMIT();

    float oacc[2][8][4];
#pragma unroll
    for (int a = 0; a < 2; a++)
#pragma unroll
        for (int b = 0; b < 8; b++)
#pragma unroll
            for (int c = 0; c < 4; c++) oacc[a][b][c] = 0.0f;

    const uint32_t aQ = sb + Q_O + (uint32_t)(mw * 32) * STQ + loA_Q;
    const uint32_t aP = sb + P_O + (uint32_t)(mw * 32) * STP + loA_P;
    const uint32_t bKb = sb + K_O + (uint32_t)(nw * 16) * STQ + loB_K;
    const uint32_t bVb = sb + V_O + (uint32_t)(nw * 64) * STV + loB_V;

    for (int ch = 0; ch < NCHUNK; ch++) {
        const uint32_t cur = (uint32_t)((ch & 1) * BUFSZ);
        __syncthreads();   // prev iter's MMA2 done before overwriting its buffer
        if (ch + 1 < NCHUNK) {
            const int nxt = ((ch + 1) & 1) * BUFSZ;
            stageK_async(sb, K_O + nxt, g_kf, (ch + 1) * BJ, tid);
            stageVt_async(sb, V_O + nxt, g_vtf, (ch + 1) * BJ, tid);
            CP_COMMIT();
            CP_WAIT(1);    // chunk ch (and Q on ch==0) complete; ch+1 in flight
        } else {
            CP_WAIT(0);
        }
        __syncthreads();

        // ---- MMA1: S[64x64] = Q.K^T, single-pass fp16 ----
        float s[2][2][4];
#pragma unroll
        for (int a = 0; a < 2; a++)
#pragma unroll
            for (int b = 0; b < 2; b++)
#pragma unroll
                for (int c = 0; c < 4; c++) s[a][b][c] = 0.0f;

        const uint32_t bK = bKb + cur;
#pragma unroll 8
        for (int ks = 0; ks < 16; ks++) {
            const uint32_t ko = (uint32_t)(ks * 32);
            uint32_t a0[4], a1[4], bh[4];
            ldsm4(a0, aQ + ko);
            ldsm4(a1, aQ + 16 * STQ + ko);
            ldsm4(bh, bK + ko);
            mma_f16(s[0][0], a0, bh[0], bh[1]); mma_f16(s[0][1], a0, bh[2], bh[3]);
            mma_f16(s[1][0], a1, bh[0], bh[1]); mma_f16(s[1][1], a1, bh[2], bh[3]);
        }

        // ---- sigmoid -> fp16 P smem ----
#pragma unroll
        for (int mf = 0; mf < 2; mf++)
#pragma unroll
            for (int nf = 0; nf < 2; nf++) {
                const float* c = s[mf][nf];
                int m = mw * 32 + mf * 16 + rr4;
                int n = nw * 16 + nf * 8 + cc2;
                *(uint32_t*)(smem + P_O + m * STP + n * 2) = h2pack(fsig(c[0]), fsig(c[1]));
                *(uint32_t*)(smem + P_O + (m + 8) * STP + n * 2) = h2pack(fsig(c[2]), fsig(c[3]));
            }
        __syncthreads();

        // ---- MMA2: O[64x256] += P.V, single-pass fp16 ----
        const uint32_t bV = bVb + cur;
#pragma unroll
        for (int ks = 0; ks < 4; ks++) {
            const uint32_t ko = (uint32_t)(ks * 32);
            uint32_t p0[4], p1[4];
            ldsm4(p0, aP + ko);
            ldsm4(p1, aP + 16 * STP + ko);
#pragma unroll
            for (int t = 0; t < 4; t++) {
                uint32_t bh[4];
                ldsm4(bh, bV + (uint32_t)(t * 16) * STV + ko);
                mma_f16(oacc[0][t * 2], p0, bh[0], bh[1]);
                mma_f16(oacc[0][t * 2 + 1], p0, bh[2], bh[3]);
                mma_f16(oacc[1][t * 2], p1, bh[0], bh[1]);
                mma_f16(oacc[1][t * 2 + 1], p1, bh[2], bh[3]);
            }
        }
    }

    // ---- epilogue ----
#pragma unroll
    for (int mf = 0; mf < 2; mf++)
#pragma unroll
        for (int j = 0; j < 8; j++) {
            const float* c = oacc[mf][j];
            int m = row0 + mw * 32 + mf * 16 + rr4;
            int col = nw * 64 + (j >> 1) * 16 + (j & 1) * 8 + cc2;
            *(float2*)(out + (size_t)m * HID + col) = make_float2(c[0], c[1]);
            *(float2*)(out + (size_t)(m + 8) * HID + col) = make_float2(c[2], c[3]);
        }
}

// ---------------------------------------------------------------------------
extern "C" void kernel_launch(void* const* d_in, const int* in_sizes, int n_in,
                              void* d_out, int out_size)
{
    const float* query = (const float*)d_in[0];
    const float* key_  = (const float*)d_in[1];
    const float* value = (const float*)d_in[2];
    const float* Wq = (const float*)d_in[3];
    const float* bq = (const float*)d_in[4];
    const float* Wk = (const float*)d_in[5];
    const float* bk = (const float*)d_in[6];
    const float* Wv = (const float*)d_in[7];
    const float* bv = (const float*)d_in[8];
    float* out = (float*)d_out;
    (void)in_sizes; (void)n_in; (void)out_size;

    float* dv;
    __half *qf, *kf, *vtf;
    cudaGetSymbolAddress((void**)&dv, g_v);
    cudaGetSymbolAddress((void**)&qf, g_qf);
    cudaGetSymbolAddress((void**)&kf, g_kf);
    cudaGetSymbolAddress((void**)&vtf, g_vtf);

    dim3 lgrid(NROWS / 64, HID / 64);
    linear_f16_kernel<<<lgrid, NTHREADS>>>(query, Wq, bq, qf);
    linear_f16_kernel<<<lgrid, NTHREADS>>>(key_,  Wk, bk, kf);
    linear_f32_kernel<<<lgrid, NTHREADS>>>(value, Wv, bv, dv);
    vt_kernel<<<dim3(NROWS / 64, HID / 64), NTHREADS>>>(dv, vtf);

    cudaFuncSetAttribute(attn_kernel, cudaFuncAttributeMaxDynamicSharedMemorySize, SMEMB);
    attn_kernel<<<NROWS / 64, NTHREADS, SMEMB>>>(out);
}

// round 8
// speedup vs baseline: 5.8818x; 1.0472x over previous
#include <cuda_runtime.h>
#include <cuda_bf16.h>
#include <cuda_fp16.h>
#include <cstdint>

#define NROWS 8192
#define HID   256
#define NTHREADS 256
#define BJ 64
#define NCHUNK (NROWS / BJ)

// ---------------- device scratch ----------------
__device__ float g_v[NROWS * HID];
__device__ __half g_qf[NROWS * HID];
__device__ __half g_kf[NROWS * HID];
__device__ __half g_vtf[HID * NROWS];   // [hid][token] fp16

typedef unsigned long long u64;
__device__ __forceinline__ u64 pk2(float x, float y) {
    u64 r; asm("mov.b64 %0, {%1,%2};" : "=l"(r) : "f"(x), "f"(y)); return r;
}
__device__ __forceinline__ void upk2(u64 v, float& x, float& y) {
    asm("mov.b64 {%0,%1}, %2;" : "=f"(x), "=f"(y) : "l"(v));
}
__device__ __forceinline__ u64 fma2(u64 a, u64 b, u64 c) {
    u64 d; asm("fma.rn.f32x2 %0, %1, %2, %3;" : "=l"(d) : "l"(a), "l"(b), "l"(c)); return d;
}
// sigmoid via HW tanh: sigma(x) = 0.5*tanh(x/2) + 0.5
__device__ __forceinline__ float fsig(float x) {
    float t; asm("tanh.approx.f32 %0, %1;" : "=f"(t) : "f"(x * 0.5f));
    return fmaf(0.5f, t, 0.5f);
}
__device__ __forceinline__ uint32_t h2pack(float a, float b) {
    __half2 h = __floats2half2_rn(a, b);
    return *(uint32_t*)&h;
}
__device__ __forceinline__ uint32_t smem_to_u32(const void* p) {
    uint32_t a;
    asm("{ .reg .u64 t; cvta.to.shared.u64 t, %1; cvt.u32.u64 %0, t; }" : "=r"(a) : "l"(p));
    return a;
}
__device__ __forceinline__ void ldsm4(uint32_t r[4], uint32_t addr) {
    asm volatile("ldmatrix.sync.aligned.m8n8.x4.shared.b16 {%0,%1,%2,%3}, [%4];"
                 : "=r"(r[0]), "=r"(r[1]), "=r"(r[2]), "=r"(r[3]) : "r"(addr));
}
__device__ __forceinline__ void mma_f16(float c[4], const uint32_t a[4], uint32_t b0, uint32_t b1) {
    asm volatile("mma.sync.aligned.m16n8k16.row.col.f32.f16.f16.f32 "
                 "{%0,%1,%2,%3}, {%4,%5,%6,%7}, {%8,%9}, {%0,%1,%2,%3};"
                 : "+f"(c[0]), "+f"(c[1]), "+f"(c[2]), "+f"(c[3])
                 : "r"(a[0]), "r"(a[1]), "r"(a[2]), "r"(a[3]), "r"(b0), "r"(b1));
}
__device__ __forceinline__ void cpasync16(uint32_t saddr, const void* g) {
    asm volatile("cp.async.cg.shared.global [%0], [%1], 16;" :: "r"(saddr), "l"(g));
}
#define CP_COMMIT() asm volatile("cp.async.commit_group;" ::: "memory")
#define CP_WAIT(N)  asm volatile("cp.async.wait_group %0;" :: "n"(N) : "memory")
#define BAR_SYNC(id, cnt)   asm volatile("bar.sync %0, %1;"   :: "r"(id), "n"(cnt) : "memory")
#define BAR_ARRIVE(id, cnt) asm volatile("bar.arrive %0, %1;" :: "r"(id), "n"(cnt) : "memory")

// ---------------- fp32 linear core (proven) ----------------
template <int EPI>
__device__ __forceinline__ void linear_body(const float* __restrict__ X, const float* __restrict__ W,
                                            const float* __restrict__ bias, float* __restrict__ out,
                                            __half* __restrict__ of16)
{
    __shared__ float sX[32 * 64];
    __shared__ float sW[32 * 64];
    const int tid = threadIdx.x;
    const int row0 = blockIdx.x * 64, col0 = blockIdx.y * 64;
    const int m0 = (tid >> 4) << 2, ac2 = (tid & 15) << 1;
    const int lm = tid & 63, lk = (tid >> 6) << 3;
    u64 acc[4][2];
#pragma unroll
    for (int r = 0; r < 4; r++) { acc[r][0] = 0ull; acc[r][1] = 0ull; }
    const float* Xp = X + (row0 + lm) * HID + lk;
    const float* Wp = W + (col0 + lm) * HID + lk;
    for (int k0 = 0; k0 < HID; k0 += 32) {
        float4 xa = *(const float4*)(Xp + k0), xb = *(const float4*)(Xp + k0 + 4);
        float4 wa = *(const float4*)(Wp + k0), wb = *(const float4*)(Wp + k0 + 4);
        sX[(lk+0)*64+lm]=xa.x; sX[(lk+1)*64+lm]=xa.y; sX[(lk+2)*64+lm]=xa.z; sX[(lk+3)*64+lm]=xa.w;
        sX[(lk+4)*64+lm]=xb.x; sX[(lk+5)*64+lm]=xb.y; sX[(lk+6)*64+lm]=xb.z; sX[(lk+7)*64+lm]=xb.w;
        sW[(lk+0)*64+lm]=wa.x; sW[(lk+1)*64+lm]=wa.y; sW[(lk+2)*64+lm]=wa.z; sW[(lk+3)*64+lm]=wa.w;
        sW[(lk+4)*64+lm]=wb.x; sW[(lk+5)*64+lm]=wb.y; sW[(lk+6)*64+lm]=wb.z; sW[(lk+7)*64+lm]=wb.w;
        __syncthreads();
#pragma unroll
        for (int kk = 0; kk < 32; kk++) {
            float4 q = *(const float4*)(sX + kk * 64 + m0);
            u64 b0 = *(const u64*)(sW + kk * 64 + ac2);
            u64 b1 = *(const u64*)(sW + kk * 64 + ac2 + 32);
            u64 a;
            a = pk2(q.x,q.x); acc[0][0]=fma2(a,b0,acc[0][0]); acc[0][1]=fma2(a,b1,acc[0][1]);
            a = pk2(q.y,q.y); acc[1][0]=fma2(a,b0,acc[1][0]); acc[1][1]=fma2(a,b1,acc[1][1]);
            a = pk2(q.z,q.z); acc[2][0]=fma2(a,b0,acc[2][0]); acc[2][1]=fma2(a,b1,acc[2][1]);
            a = pk2(q.w,q.w); acc[3][0]=fma2(a,b0,acc[3][0]); acc[3][1]=fma2(a,b1,acc[3][1]);
        }
        __syncthreads();
    }
    const int c0 = col0 + ac2;
    const float b0 = bias[c0], b1 = bias[c0+1], b2 = bias[c0+32], b3 = bias[c0+33];
#pragma unroll
    for (int r = 0; r < 4; r++) {
        float x, y;
        size_t ro = (size_t)(row0 + m0 + r) * HID;
        upk2(acc[r][0], x, y);
        if (EPI == 0) *(float2*)(out + ro + c0) = make_float2(x + b0, y + b1);
        else          *(uint32_t*)(of16 + ro + c0) = h2pack(x + b0, y + b1);
        upk2(acc[r][1], x, y);
        if (EPI == 0) *(float2*)(out + ro + c0 + 32) = make_float2(x + b2, y + b3);
        else          *(uint32_t*)(of16 + ro + c0 + 32) = h2pack(x + b2, y + b3);
    }
}

__global__ __launch_bounds__(NTHREADS)
void linear_f32_kernel(const float* __restrict__ X, const float* __restrict__ W,
                       const float* __restrict__ bias, float* __restrict__ out)
{ linear_body<0>(X, W, bias, out, nullptr); }

__global__ __launch_bounds__(NTHREADS)
void linear_f16_kernel(const float* __restrict__ X, const float* __restrict__ W,
                       const float* __restrict__ bias, __half* __restrict__ of16)
{ linear_body<1>(X, W, bias, nullptr, of16); }

// ---------------- transpose V -> fp16 [hid][token] ----------------
__global__ __launch_bounds__(NTHREADS)
void vt_kernel(const float* __restrict__ v, __half* __restrict__ vtf)
{
    __shared__ float tile[64 * 64];
    const int j0 = blockIdx.x * 64, c0 = blockIdx.y * 64;
    const int tid = threadIdx.x;
    const int r = tid >> 4, c4 = (tid & 15) * 4;
#pragma unroll
    for (int i = 0; i < 4; i++)
        *(float4*)(tile + (r + 16*i) * 64 + c4) = *(const float4*)(v + (j0 + r + 16*i) * HID + c0 + c4);
    __syncthreads();
    const int n = tid >> 2, jb = (tid & 3) * 16;
    uint32_t h[8];
#pragma unroll
    for (int i = 0; i < 16; i += 2)
        h[i >> 1] = h2pack(tile[(jb+i)*64 + n], tile[(jb+i+1)*64 + n]);
    size_t o = (size_t)(c0 + n) * NROWS + j0 + jb;
    *(uint4*)(vtf + o)     = make_uint4(h[0], h[1], h[2], h[3]);
    *(uint4*)(vtf + o + 8) = make_uint4(h[4], h[5], h[6], h[7]);
}

// ---------------- warp-specialized HMMA attention ----------------
// Group A (warps 0-7): MMA1 + sigmoid -> P ring.  Group B (warps 8-15): MMA2.
// Q 64x256 stride 528; K 2 bufs 64x256 stride 528; Vt 2 bufs 256x64 stride 144;
// P 2 bufs 64x64 fp16 stride 144.
#define STQ 528
#define STP 144
#define STV 144
#define Q_O    0
#define K_O    33792           // + (i&1)*KBUF
#define KBUF   33792
#define V_O    101376          // + (i&1)*VBUF
#define VBUF   36864
#define P_O    175104          // + (i&1)*PBUF
#define PBUF   9216
#define SMEMB  193536

__device__ __forceinline__ void stageK_async(uint32_t sb, int off, const __half* src,
                                             int r0, int t) {
    for (int f = t; f < 2048; f += 256) {
        int row = f >> 5, u = f & 31;
        cpasync16(sb + off + row * STQ + u * 16, src + (size_t)(r0 + row) * HID + u * 8);
    }
}
__device__ __forceinline__ void stageVt_async(uint32_t sb, int off, const __half* src,
                                              int j0, int t) {
    for (int f = t; f < 2048; f += 256) {
        int row = f >> 3, u = f & 7;
        cpasync16(sb + off + row * STV + u * 16, src + (size_t)row * NROWS + j0 + u * 8);
    }
}

__global__ __launch_bounds__(512)
void attn_kernel(float* __restrict__ out)
{
    extern __shared__ __align__(128) char smem[];
    const uint32_t sb = smem_to_u32(smem);
    const int tid = threadIdx.x, wid = tid >> 5, lane = tid & 31;
    const int t256 = tid & 255;
    const int w = wid & 7;
    const int mw = w & 1, nw = w >> 1;
    const int row0 = blockIdx.x * 64;
    const int g = lane >> 3, rr = lane & 7;
    const int rr4 = lane >> 2, cc2 = (lane & 3) * 2;

    const uint32_t loA_Q = (uint32_t)((rr + (g & 1) * 8) * STQ + (g >> 1) * 16);
    const uint32_t loA_P = (uint32_t)((rr + (g & 1) * 8) * STP + (g >> 1) * 16);
    const uint32_t loB_K = (uint32_t)((rr + (g >> 1) * 8) * STQ + (g & 1) * 16);
    const uint32_t loB_V = (uint32_t)((rr + (g >> 1) * 8) * STV + (g & 1) * 16);

    if (wid < 8) {
        // ================= group A: MMA1 + sigmoid =================
        stageK_async(sb, Q_O, g_qf, row0, t256);
        stageK_async(sb, K_O, g_kf, 0, t256);
        CP_COMMIT();

        const uint32_t aQ  = sb + Q_O + (uint32_t)(mw * 32) * STQ + loA_Q;
        const uint32_t bKb = sb + K_O + (uint32_t)(nw * 16) * STQ + loB_K;

        for (int i = 0; i < NCHUNK; i++) {
            CP_WAIT(0);
            BAR_SYNC(1, 256);                       // K[i&1] (+Q) visible to group A
            if (i + 1 < NCHUNK) {
                stageK_async(sb, K_O + ((i + 1) & 1) * KBUF, g_kf, (i + 1) * BJ, t256);
                CP_COMMIT();
            }

            float s[2][2][4];
#pragma unroll
            for (int a = 0; a < 2; a++)
#pragma unroll
                for (int b = 0; b < 2; b++)
#pragma unroll
                    for (int c = 0; c < 4; c++) s[a][b][c] = 0.0f;

            const uint32_t bK = bKb + (uint32_t)((i & 1) * KBUF);
#pragma unroll 8
            for (int ks = 0; ks < 16; ks++) {
                const uint32_t ko = (uint32_t)(ks * 32);
                uint32_t a0[4], a1[4], bh[4];
                ldsm4(a0, aQ + ko);
                ldsm4(a1, aQ + 16 * STQ + ko);
                ldsm4(bh, bK + ko);
                mma_f16(s[0][0], a0, bh[0], bh[1]); mma_f16(s[0][1], a0, bh[2], bh[3]);
                mma_f16(s[1][0], a1, bh[0], bh[1]); mma_f16(s[1][1], a1, bh[2], bh[3]);
            }

            // sigmoid -> packed fp16 (regs)
            uint32_t pk[2][2][2];
#pragma unroll
            for (int mf = 0; mf < 2; mf++)
#pragma unroll
                for (int nf = 0; nf < 2; nf++) {
                    const float* c = s[mf][nf];
                    pk[mf][nf][0] = h2pack(fsig(c[0]), fsig(c[1]));
                    pk[mf][nf][1] = h2pack(fsig(c[2]), fsig(c[3]));
                }

            if (i >= 2) BAR_SYNC(5 + (i & 1), 512); // P[i&1] drained by group B
            const uint32_t Pb = (uint32_t)(P_O + (i & 1) * PBUF);
#pragma unroll
            for (int mf = 0; mf < 2; mf++)
#pragma unroll
                for (int nf = 0; nf < 2; nf++) {
                    int m = mw * 32 + mf * 16 + rr4;
                    int n = nw * 16 + nf * 8 + cc2;
                    *(uint32_t*)(smem + Pb + m * STP + n * 2) = pk[mf][nf][0];
                    *(uint32_t*)(smem + Pb + (m + 8) * STP + n * 2) = pk[mf][nf][1];
                }
            __threadfence_block();
            BAR_ARRIVE(3 + (i & 1), 512);           // P[i&1] full
        }
    } else {
        // ================= group B: MMA2 =================
        stageVt_async(sb, V_O, g_vtf, 0, t256);
        CP_COMMIT();

        float oacc[2][8][4];
#pragma unroll
        for (int a = 0; a < 2; a++)
#pragma unroll
            for (int b = 0; b < 8; b++)
#pragma unroll
                for (int c = 0; c < 4; c++) oacc[a][b][c] = 0.0f;

        const uint32_t aPb = sb + P_O + (uint32_t)(mw * 32) * STP + loA_P;
        const uint32_t bVb = sb + V_O + (uint32_t)(nw * 64) * STV + loB_V;

        for (int i = 0; i < NCHUNK; i++) {
            BAR_SYNC(3 + (i & 1), 512);             // P[i&1] full
            CP_WAIT(0);
            BAR_SYNC(2, 256);                       // V[i&1] visible to group B
            if (i + 1 < NCHUNK) {
                stageVt_async(sb, V_O + ((i + 1) & 1) * VBUF, g_vtf, (i + 1) * BJ, t256);
                CP_COMMIT();
            }

            const uint32_t aP = aPb + (uint32_t)((i & 1) * PBUF);
            const uint32_t bV = bVb + (uint32_t)((i & 1) * VBUF);
#pragma unroll
            for (int ks = 0; ks < 4; ks++) {
                const uint32_t ko = (uint32_t)(ks * 32);
                uint32_t p0[4], p1[4];
                ldsm4(p0, aP + ko);
                ldsm4(p1, aP + 16 * STP + ko);
#pragma unroll
                for (int t = 0; t < 4; t++) {
                    uint32_t bh[4];
                    ldsm4(bh, bV + (uint32_t)(t * 16) * STV + ko);
                    mma_f16(oacc[0][t * 2], p0, bh[0], bh[1]);
                    mma_f16(oacc[0][t * 2 + 1], p0, bh[2], bh[3]);
                    mma_f16(oacc[1][t * 2], p1, bh[0], bh[1]);
                    mma_f16(oacc[1][t * 2 + 1], p1, bh[2], bh[3]);
                }
            }
            BAR_ARRIVE(5 + (i & 1), 512);           // P[i&1] empty
        }

        // epilogue (group B owns O)
#pragma unroll
        for (int mf = 0; mf < 2; mf++)
#pragma unroll
            for (int j = 0; j < 8; j++) {
                const float* c = oacc[mf][j];
                int m = row0 + mw * 32 + mf * 16 + rr4;
                int col = nw * 64 + (j >> 1) * 16 + (j & 1) * 8 + cc2;
                *(float2*)(out + (size_t)m * HID + col) = make_float2(c[0], c[1]);
                *(float2*)(out + (size_t)(m + 8) * HID + col) = make_float2(c[2], c[3]);
            }
    }
}

// ---------------------------------------------------------------------------
extern "C" void kernel_launch(void* const* d_in, const int* in_sizes, int n_in,
                              void* d_out, int out_size)
{
    const float* query = (const float*)d_in[0];
    const float* key_  = (const float*)d_in[1];
    const float* value = (const float*)d_in[2];
    const float* Wq = (const float*)d_in[3];
    const float* bq = (const float*)d_in[4];
    const float* Wk = (const float*)d_in[5];
    const float* bk = (const float*)d_in[6];
    const float* Wv = (const float*)d_in[7];
    const float* bv = (const float*)d_in[8];
    float* out = (float*)d_out;
    (void)in_sizes; (void)n_in; (void)out_size;

    float* dv;
    __half *qf, *kf, *vtf;
    cudaGetSymbolAddress((void**)&dv, g_v);
    cudaGetSymbolAddress((void**)&qf, g_qf);
    cudaGetSymbolAddress((void**)&kf, g_kf);
    cudaGetSymbolAddress((void**)&vtf, g_vtf);

    dim3 lgrid(NROWS / 64, HID / 64);
    linear_f16_kernel<<<lgrid, NTHREADS>>>(query, Wq, bq, qf);
    linear_f16_kernel<<<lgrid, NTHREADS>>>(key_,  Wk, bk, kf);
    linear_f32_kernel<<<lgrid, NTHREADS>>>(value, Wv, bv, dv);
    vt_kernel<<<dim3(NROWS / 64, HID / 64), NTHREADS>>>(dv, vtf);

    cudaFuncSetAttribute(attn_kernel, cudaFuncAttributeMaxDynamicSharedMemorySize, SMEMB);
    attn_kernel<<<NROWS / 64, 512, SMEMB>>>(out);
}

// round 9
// speedup vs baseline: 7.9972x; 1.3596x over previous
#include <cuda_runtime.h>
#include <cuda_bf16.h>
#include <cuda_fp16.h>
#include <cstdint>

#define NROWS 8192
#define HID   256
#define NTHREADS 256
#define BJ 64
#define JSPLIT 8
#define NCHSEG (NROWS / BJ / JSPLIT)   // 16 chunks per CTA

// ---------------- device scratch ----------------
__device__ float g_v[NROWS * HID];
__device__ __half g_qf[NROWS * HID];
__device__ __half g_kf[NROWS * HID];
__device__ __half g_vtf[HID * NROWS];            // [hid][token] fp16
__device__ float g_part[(JSPLIT - 1) * NROWS * HID];  // partial O for jseg 1..7

// sigmoid via HW tanh
__device__ __forceinline__ float fsig(float x) {
    float t; asm("tanh.approx.f32 %0, %1;" : "=f"(t) : "f"(x * 0.5f));
    return fmaf(0.5f, t, 0.5f);
}
__device__ __forceinline__ uint32_t h2pack(float a, float b) {
    __half2 h = __floats2half2_rn(a, b);
    return *(uint32_t*)&h;
}
__device__ __forceinline__ uint32_t smem_to_u32(const void* p) {
    uint32_t a;
    asm("{ .reg .u64 t; cvta.to.shared.u64 t, %1; cvt.u32.u64 %0, t; }" : "=r"(a) : "l"(p));
    return a;
}
__device__ __forceinline__ void ldsm4(uint32_t r[4], uint32_t addr) {
    asm volatile("ldmatrix.sync.aligned.m8n8.x4.shared.b16 {%0,%1,%2,%3}, [%4];"
                 : "=r"(r[0]), "=r"(r[1]), "=r"(r[2]), "=r"(r[3]) : "r"(addr));
}
__device__ __forceinline__ void mma_f16(float c[4], const uint32_t a[4], uint32_t b0, uint32_t b1) {
    asm volatile("mma.sync.aligned.m16n8k16.row.col.f32.f16.f16.f32 "
                 "{%0,%1,%2,%3}, {%4,%5,%6,%7}, {%8,%9}, {%0,%1,%2,%3};"
                 : "+f"(c[0]), "+f"(c[1]), "+f"(c[2]), "+f"(c[3])
                 : "r"(a[0]), "r"(a[1]), "r"(a[2]), "r"(a[3]), "r"(b0), "r"(b1));
}
__device__ __forceinline__ void cpasync16(uint32_t saddr, const void* g) {
    asm volatile("cp.async.cg.shared.global [%0], [%1], 16;" :: "r"(saddr), "l"(g));
}
#define CP_COMMIT() asm volatile("cp.async.commit_group;" ::: "memory")
#define CP_WAIT(N)  asm volatile("cp.async.wait_group %0;" :: "n"(N) : "memory")
#define BAR_SYNC(id, cnt)   asm volatile("bar.sync %0, %1;"   :: "r"(id), "n"(cnt) : "memory")
#define BAR_ARRIVE(id, cnt) asm volatile("bar.arrive %0, %1;" :: "r"(id), "n"(cnt) : "memory")

// ================= HMMA linear: out = X @ W^T + b =================
// grid (128, 3): y=0 -> Q (fp16 out), y=1 -> K (fp16 out), y=2 -> V (fp32 out)
// smem: X tile 64x256 fp16 stride 528 ; W 256x256 fp16 stride 528
#define LST 528
#define LX_O 0
#define LW_O 33792
#define LSMEMB 168960

__global__ __launch_bounds__(NTHREADS)
void linear_hmma_kernel(const float* __restrict__ Xq, const float* __restrict__ Xk,
                        const float* __restrict__ Xv,
                        const float* __restrict__ Wq, const float* __restrict__ Wk,
                        const float* __restrict__ Wv,
                        const float* __restrict__ bq, const float* __restrict__ bk,
                        const float* __restrict__ bv,
                        __half* __restrict__ qf, __half* __restrict__ kf,
                        float* __restrict__ vf)
{
    extern __shared__ __align__(128) char smem[];
    const uint32_t sb = smem_to_u32(smem);
    const int tid = threadIdx.x, warp = tid >> 5, lane = tid & 31;
    const int mw = warp & 1, nw = warp >> 1;
    const int row0 = blockIdx.x * 64;
    const int which = blockIdx.y;
    const int g = lane >> 3, rr = lane & 7;
    const int rr4 = lane >> 2, cc2 = (lane & 3) * 2;

    const float* X = which == 0 ? Xq : (which == 1 ? Xk : Xv);
    const float* W = which == 0 ? Wq : (which == 1 ? Wk : Wv);
    const float* bias = which == 0 ? bq : (which == 1 ? bk : bv);

    // stage X tile (64x256) fp32 -> fp16 smem
    for (int f = tid; f < 4096; f += NTHREADS) {
        int row = f >> 6, c4 = (f & 63) << 2;
        float4 v = *(const float4*)(X + (size_t)(row0 + row) * HID + c4);
        *(uint2*)(smem + LX_O + row * LST + c4 * 2) =
            make_uint2(h2pack(v.x, v.y), h2pack(v.z, v.w));
    }
    // stage W (256x256) fp32 -> fp16 smem
    for (int f = tid; f < 16384; f += NTHREADS) {
        int row = f >> 6, c4 = (f & 63) << 2;
        float4 v = *(const float4*)(W + (size_t)row * HID + c4);
        *(uint2*)(smem + LW_O + row * LST + c4 * 2) =
            make_uint2(h2pack(v.x, v.y), h2pack(v.z, v.w));
    }
    __syncthreads();

    const uint32_t loA = (uint32_t)((rr + (g & 1) * 8) * LST + (g >> 1) * 16);
    const uint32_t loB = (uint32_t)((rr + (g >> 1) * 8) * LST + (g & 1) * 16);
    const uint32_t aX = sb + LX_O + (uint32_t)(mw * 32) * LST + loA;
    const uint32_t bW = sb + LW_O + (uint32_t)(nw * 64) * LST + loB;

    float acc[2][8][4];
#pragma unroll
    for (int a = 0; a < 2; a++)
#pragma unroll
        for (int b = 0; b < 8; b++)
#pragma unroll
            for (int c = 0; c < 4; c++) acc[a][b][c] = 0.0f;

#pragma unroll 4
    for (int ks = 0; ks < 16; ks++) {
        const uint32_t ko = (uint32_t)(ks * 32);
        uint32_t a0[4], a1[4];
        ldsm4(a0, aX + ko);
        ldsm4(a1, aX + 16 * LST + ko);
#pragma unroll
        for (int t = 0; t < 4; t++) {
            uint32_t bh[4];
            ldsm4(bh, bW + (uint32_t)(t * 16) * LST + ko);
            mma_f16(acc[0][t * 2], a0, bh[0], bh[1]);
            mma_f16(acc[0][t * 2 + 1], a0, bh[2], bh[3]);
            mma_f16(acc[1][t * 2], a1, bh[0], bh[1]);
            mma_f16(acc[1][t * 2 + 1], a1, bh[2], bh[3]);
        }
    }

    // epilogue: + bias, write
#pragma unroll
    for (int mf = 0; mf < 2; mf++)
#pragma unroll
        for (int j = 0; j < 8; j++) {
            const float* c = acc[mf][j];
            int m = row0 + mw * 32 + mf * 16 + rr4;
            int col = nw * 64 + (j >> 1) * 16 + (j & 1) * 8 + cc2;
            float b0 = bias[col], b1 = bias[col + 1];
            if (which == 2) {
                *(float2*)(vf + (size_t)m * HID + col) = make_float2(c[0] + b0, c[1] + b1);
                *(float2*)(vf + (size_t)(m + 8) * HID + col) = make_float2(c[2] + b0, c[3] + b1);
            } else {
                __half* dst = which == 0 ? qf : kf;
                *(uint32_t*)(dst + (size_t)m * HID + col) = h2pack(c[0] + b0, c[1] + b1);
                *(uint32_t*)(dst + (size_t)(m + 8) * HID + col) = h2pack(c[2] + b0, c[3] + b1);
            }
        }
}

// ---------------- transpose V -> fp16 [hid][token] ----------------
__global__ __launch_bounds__(NTHREADS)
void vt_kernel(const float* __restrict__ v, __half* __restrict__ vtf)
{
    __shared__ float tile[64 * 64];
    const int j0 = blockIdx.x * 64, c0 = blockIdx.y * 64;
    const int tid = threadIdx.x;
    const int r = tid >> 4, c4 = (tid & 15) * 4;
#pragma unroll
    for (int i = 0; i < 4; i++)
        *(float4*)(tile + (r + 16*i) * 64 + c4) = *(const float4*)(v + (j0 + r + 16*i) * HID + c0 + c4);
    __syncthreads();
    const int n = tid >> 2, jb = (tid & 3) * 16;
    uint32_t h[8];
#pragma unroll
    for (int i = 0; i < 16; i += 2)
        h[i >> 1] = h2pack(tile[(jb+i)*64 + n], tile[(jb+i+1)*64 + n]);
    size_t o = (size_t)(c0 + n) * NROWS + j0 + jb;
    *(uint4*)(vtf + o)     = make_uint4(h[0], h[1], h[2], h[3]);
    *(uint4*)(vtf + o + 8) = make_uint4(h[4], h[5], h[6], h[7]);
}

// ---------------- warp-specialized HMMA attention (j-split x8) ----------------
#define STQ 528
#define STP 144
#define STV 144
#define Q_O    0
#define K_O    33792
#define KBUF   33792
#define V_O    101376
#define VBUF   36864
#define P_O    175104
#define PBUF   9216
#define SMEMB  193536

__device__ __forceinline__ void stageK_async(uint32_t sb, int off, const __half* src,
                                             int r0, int t) {
    for (int f = t; f < 2048; f += 256) {
        int row = f >> 5, u = f & 31;
        cpasync16(sb + off + row * STQ + u * 16, src + (size_t)(r0 + row) * HID + u * 8);
    }
}
__device__ __forceinline__ void stageVt_async(uint32_t sb, int off, const __half* src,
                                              int j0, int t) {
    for (int f = t; f < 2048; f += 256) {
        int row = f >> 3, u = f & 7;
        cpasync16(sb + off + row * STV + u * 16, src + (size_t)row * NROWS + j0 + u * 8);
    }
}

__global__ __launch_bounds__(512)
void attn_kernel(float* __restrict__ out)
{
    extern __shared__ __align__(128) char smem[];
    const uint32_t sb = smem_to_u32(smem);
    const int tid = threadIdx.x, wid = tid >> 5, lane = tid & 31;
    const int t256 = tid & 255;
    const int w = wid & 7;
    const int mw = w & 1, nw = w >> 1;
    const int row0 = blockIdx.x * 64;
    const int jbase = blockIdx.y * (NROWS / JSPLIT);
    float* outp = (blockIdx.y == 0) ? out
                : g_part + (size_t)(blockIdx.y - 1) * NROWS * HID;
    const int g = lane >> 3, rr = lane & 7;
    const int rr4 = lane >> 2, cc2 = (lane & 3) * 2;

    const uint32_t loA_Q = (uint32_t)((rr + (g & 1) * 8) * STQ + (g >> 1) * 16);
    const uint32_t loA_P = (uint32_t)((rr + (g & 1) * 8) * STP + (g >> 1) * 16);
    const uint32_t loB_K = (uint32_t)((rr + (g >> 1) * 8) * STQ + (g & 1) * 16);
    const uint32_t loB_V = (uint32_t)((rr + (g >> 1) * 8) * STV + (g & 1) * 16);

    if (wid < 8) {
        // ============ group A: MMA1 + sigmoid -> P ring ============
        stageK_async(sb, Q_O, g_qf, row0, t256);
        stageK_async(sb, K_O, g_kf, jbase, t256);
        CP_COMMIT();

        const uint32_t aQ  = sb + Q_O + (uint32_t)(mw * 32) * STQ + loA_Q;
        const uint32_t bKb = sb + K_O + (uint32_t)(nw * 16) * STQ + loB_K;

        for (int i = 0; i < NCHSEG; i++) {
            CP_WAIT(0);
            BAR_SYNC(1, 256);
            if (i + 1 < NCHSEG) {
                stageK_async(sb, K_O + ((i + 1) & 1) * KBUF, g_kf, jbase + (i + 1) * BJ, t256);
                CP_COMMIT();
            }

            float s[2][2][4];
#pragma unroll
            for (int a = 0; a < 2; a++)
#pragma unroll
                for (int b = 0; b < 2; b++)
#pragma unroll
                    for (int c = 0; c < 4; c++) s[a][b][c] = 0.0f;

            const uint32_t bK = bKb + (uint32_t)((i & 1) * KBUF);
#pragma unroll 8
            for (int ks = 0; ks < 16; ks++) {
                const uint32_t ko = (uint32_t)(ks * 32);
                uint32_t a0[4], a1[4], bh[4];
                ldsm4(a0, aQ + ko);
                ldsm4(a1, aQ + 16 * STQ + ko);
                ldsm4(bh, bK + ko);
                mma_f16(s[0][0], a0, bh[0], bh[1]); mma_f16(s[0][1], a0, bh[2], bh[3]);
                mma_f16(s[1][0], a1, bh[0], bh[1]); mma_f16(s[1][1], a1, bh[2], bh[3]);
            }

            uint32_t pk[2][2][2];
#pragma unroll
            for (int mf = 0; mf < 2; mf++)
#pragma unroll
                for (int nf = 0; nf < 2; nf++) {
                    const float* c = s[mf][nf];
                    pk[mf][nf][0] = h2pack(fsig(c[0]), fsig(c[1]));
                    pk[mf][nf][1] = h2pack(fsig(c[2]), fsig(c[3]));
                }

            if (i >= 2) BAR_SYNC(5 + (i & 1), 512);
            const uint32_t Pb = (uint32_t)(P_O + (i & 1) * PBUF);
#pragma unroll
            for (int mf = 0; mf < 2; mf++)
#pragma unroll
                for (int nf = 0; nf < 2; nf++) {
                    int m = mw * 32 + mf * 16 + rr4;
                    int n = nw * 16 + nf * 8 + cc2;
                    *(uint32_t*)(smem + Pb + m * STP + n * 2) = pk[mf][nf][0];
                    *(uint32_t*)(smem + Pb + (m + 8) * STP + n * 2) = pk[mf][nf][1];
                }
            __threadfence_block();
            BAR_ARRIVE(3 + (i & 1), 512);
        }
    } else {
        // ============ group B: MMA2 ============
        stageVt_async(sb, V_O, g_vtf, jbase, t256);
        CP_COMMIT();

        float oacc[2][8][4];
#pragma unroll
        for (int a = 0; a < 2; a++)
#pragma unroll
            for (int b = 0; b < 8; b++)
#pragma unroll
                for (int c = 0; c < 4; c++) oacc[a][b][c] = 0.0f;

        const uint32_t aPb = sb + P_O + (uint32_t)(mw * 32) * STP + loA_P;
        const uint32_t bVb = sb + V_O + (uint32_t)(nw * 64) * STV + loB_V;

        for (int i = 0; i < NCHSEG; i++) {
            BAR_SYNC(3 + (i & 1), 512);
            CP_WAIT(0);
            BAR_SYNC(2, 256);
            if (i + 1 < NCHSEG) {
                stageVt_async(sb, V_O + ((i + 1) & 1) * VBUF, g_vtf, jbase + (i + 1) * BJ, t256);
                CP_COMMIT();
            }

            const uint32_t aP = aPb + (uint32_t)((i & 1) * PBUF);
            const uint32_t bV = bVb + (uint32_t)((i & 1) * VBUF);
#pragma unroll
            for (int ks = 0; ks < 4; ks++) {
                const uint32_t ko = (uint32_t)(ks * 32);
                uint32_t p0[4], p1[4];
                ldsm4(p0, aP + ko);
                ldsm4(p1, aP + 16 * STP + ko);
#pragma unroll
                for (int t = 0; t < 4; t++) {
                    uint32_t bh[4];
                    ldsm4(bh, bV + (uint32_t)(t * 16) * STV + ko);
                    mma_f16(oacc[0][t * 2], p0, bh[0], bh[1]);
                    mma_f16(oacc[0][t * 2 + 1], p0, bh[2], bh[3]);
                    mma_f16(oacc[1][t * 2], p1, bh[0], bh[1]);
                    mma_f16(oacc[1][t * 2 + 1], p1, bh[2], bh[3]);
                }
            }
            BAR_ARRIVE(5 + (i & 1), 512);
        }

#pragma unroll
        for (int mf = 0; mf < 2; mf++)
#pragma unroll
            for (int j = 0; j < 8; j++) {
                const float* c = oacc[mf][j];
                int m = row0 + mw * 32 + mf * 16 + rr4;
                int col = nw * 64 + (j >> 1) * 16 + (j & 1) * 8 + cc2;
                *(float2*)(outp + (size_t)m * HID + col) = make_float2(c[0], c[1]);
                *(float2*)(outp + (size_t)(m + 8) * HID + col) = make_float2(c[2], c[3]);
            }
    }
}

// ---------------- deterministic reduce of j-split partials ----------------
__global__ __launch_bounds__(NTHREADS)
void reduce_kernel(float* __restrict__ out)
{
    size_t i = ((size_t)blockIdx.x * NTHREADS + threadIdx.x) * 4;
    float4 a = *(float4*)(out + i);
#pragma unroll
    for (int s = 0; s < JSPLIT - 1; s++) {
        float4 b = *(const float4*)(g_part + (size_t)s * NROWS * HID + i);
        a.x += b.x; a.y += b.y; a.z += b.z; a.w += b.w;
    }
    *(float4*)(out + i) = a;
}

// ---------------------------------------------------------------------------
extern "C" void kernel_launch(void* const* d_in, const int* in_sizes, int n_in,
                              void* d_out, int out_size)
{
    const float* query = (const float*)d_in[0];
    const float* key_  = (const float*)d_in[1];
    const float* value = (const float*)d_in[2];
    const float* Wq = (const float*)d_in[3];
    const float* bq = (const float*)d_in[4];
    const float* Wk = (const float*)d_in[5];
    const float* bk = (const float*)d_in[6];
    const float* Wv = (const float*)d_in[7];
    const float* bv = (const float*)d_in[8];
    float* out = (float*)d_out;
    (void)in_sizes; (void)n_in; (void)out_size;

    float* dv;
    __half *qf, *kf, *vtf;
    cudaGetSymbolAddress((void**)&dv, g_v);
    cudaGetSymbolAddress((void**)&qf, g_qf);
    cudaGetSymbolAddress((void**)&kf, g_kf);
    cudaGetSymbolAddress((void**)&vtf, g_vtf);

    cudaFuncSetAttribute(linear_hmma_kernel, cudaFuncAttributeMaxDynamicSharedMemorySize, LSMEMB);
    linear_hmma_kernel<<<dim3(NROWS / 64, 3), NTHREADS, LSMEMB>>>(
        query, key_, value, Wq, Wk, Wv, bq, bk, bv, qf, kf, dv);

    vt_kernel<<<dim3(NROWS / 64, HID / 64), NTHREADS>>>(dv, vtf);

    cudaFuncSetAttribute(attn_kernel, cudaFuncAttributeMaxDynamicSharedMemorySize, SMEMB);
    attn_kernel<<<dim3(NROWS / 64, JSPLIT), 512, SMEMB>>>(out);

    reduce_kernel<<<NROWS * HID / 4 / NTHREADS, NTHREADS>>>(out);
}

// round 10
// speedup vs baseline: 9.5392x; 1.1928x over previous
#include <cuda_runtime.h>
#include <cuda_bf16.h>
#include <cuda_fp16.h>
#include <cstdint>

#define NROWS 8192
#define HID   256
#define NTHREADS 256
#define BJ 64
#define JSPLIT 8
#define NCHSEG (NROWS / BJ / JSPLIT)   // 16 chunks per CTA

// ---------------- device scratch ----------------
__device__ __half g_qf[NROWS * HID];
__device__ __half g_kf[NROWS * HID];
__device__ __half g_vtf[HID * NROWS];                  // [hid][token] fp16
__device__ __half g_ph[(JSPLIT - 1) * NROWS * HID];    // fp16 partial O, jseg 1..7

// sigmoid via HW tanh
__device__ __forceinline__ float fsig(float x) {
    float t; asm("tanh.approx.f32 %0, %1;" : "=f"(t) : "f"(x * 0.5f));
    return fmaf(0.5f, t, 0.5f);
}
__device__ __forceinline__ uint32_t h2pack(float a, float b) {
    __half2 h = __floats2half2_rn(a, b);
    return *(uint32_t*)&h;
}
__device__ __forceinline__ uint32_t smem_to_u32(const void* p) {
    uint32_t a;
    asm("{ .reg .u64 t; cvta.to.shared.u64 t, %1; cvt.u32.u64 %0, t; }" : "=r"(a) : "l"(p));
    return a;
}
__device__ __forceinline__ void ldsm4(uint32_t r[4], uint32_t addr) {
    asm volatile("ldmatrix.sync.aligned.m8n8.x4.shared.b16 {%0,%1,%2,%3}, [%4];"
                 : "=r"(r[0]), "=r"(r[1]), "=r"(r[2]), "=r"(r[3]) : "r"(addr));
}
__device__ __forceinline__ void mma_f16(float c[4], const uint32_t a[4], uint32_t b0, uint32_t b1) {
    asm volatile("mma.sync.aligned.m16n8k16.row.col.f32.f16.f16.f32 "
                 "{%0,%1,%2,%3}, {%4,%5,%6,%7}, {%8,%9}, {%0,%1,%2,%3};"
                 : "+f"(c[0]), "+f"(c[1]), "+f"(c[2]), "+f"(c[3])
                 : "r"(a[0]), "r"(a[1]), "r"(a[2]), "r"(a[3]), "r"(b0), "r"(b1));
}
__device__ __forceinline__ void cpasync16(uint32_t saddr, const void* g) {
    asm volatile("cp.async.cg.shared.global [%0], [%1], 16;" :: "r"(saddr), "l"(g));
}
#define CP_COMMIT() asm volatile("cp.async.commit_group;" ::: "memory")
#define CP_WAIT(N)  asm volatile("cp.async.wait_group %0;" :: "n"(N) : "memory")
#define BAR_SYNC(id, cnt)   asm volatile("bar.sync %0, %1;"   :: "r"(id), "n"(cnt) : "memory")
#define BAR_ARRIVE(id, cnt) asm volatile("bar.arrive %0, %1;" :: "r"(id), "n"(cnt) : "memory")

// ================= HMMA linear: out = X @ W^T + b =================
// grid (128, 3): y=0 -> Q (fp16), y=1 -> K (fp16), y=2 -> V^T (fp16, [hid][token])
#define LST 528
#define LX_O 0
#define LW_O 33792
#define LSMEMB 168960

__global__ __launch_bounds__(NTHREADS)
void linear_hmma_kernel(const float* __restrict__ Xq, const float* __restrict__ Xk,
                        const float* __restrict__ Xv,
                        const float* __restrict__ Wq, const float* __restrict__ Wk,
                        const float* __restrict__ Wv,
                        const float* __restrict__ bq, const float* __restrict__ bk,
                        const float* __restrict__ bv,
                        __half* __restrict__ qf, __half* __restrict__ kf,
                        __half* __restrict__ vtf)
{
    extern __shared__ __align__(128) char smem[];
    const uint32_t sb = smem_to_u32(smem);
    const int tid = threadIdx.x, warp = tid >> 5, lane = tid & 31;
    const int mw = warp & 1, nw = warp >> 1;
    const int row0 = blockIdx.x * 64;
    const int which = blockIdx.y;
    const int g = lane >> 3, rr = lane & 7;
    const int rr4 = lane >> 2, cc2 = (lane & 3) * 2;

    const float* X = which == 0 ? Xq : (which == 1 ? Xk : Xv);
    const float* W = which == 0 ? Wq : (which == 1 ? Wk : Wv);
    const float* bias = which == 0 ? bq : (which == 1 ? bk : bv);

    // stage X tile (64x256) fp32 -> fp16 smem
    for (int f = tid; f < 4096; f += NTHREADS) {
        int row = f >> 6, c4 = (f & 63) << 2;
        float4 v = *(const float4*)(X + (size_t)(row0 + row) * HID + c4);
        *(uint2*)(smem + LX_O + row * LST + c4 * 2) =
            make_uint2(h2pack(v.x, v.y), h2pack(v.z, v.w));
    }
    // stage W (256x256) fp32 -> fp16 smem
    for (int f = tid; f < 16384; f += NTHREADS) {
        int row = f >> 6, c4 = (f & 63) << 2;
        float4 v = *(const float4*)(W + (size_t)row * HID + c4);
        *(uint2*)(smem + LW_O + row * LST + c4 * 2) =
            make_uint2(h2pack(v.x, v.y), h2pack(v.z, v.w));
    }
    __syncthreads();

    const uint32_t loA = (uint32_t)((rr + (g & 1) * 8) * LST + (g >> 1) * 16);
    const uint32_t loB = (uint32_t)((rr + (g >> 1) * 8) * LST + (g & 1) * 16);
    const uint32_t aX = sb + LX_O + (uint32_t)(mw * 32) * LST + loA;
    const uint32_t bW = sb + LW_O + (uint32_t)(nw * 64) * LST + loB;

    float acc[2][8][4];
#pragma unroll
    for (int a = 0; a < 2; a++)
#pragma unroll
        for (int b = 0; b < 8; b++)
#pragma unroll
            for (int c = 0; c < 4; c++) acc[a][b][c] = 0.0f;

#pragma unroll 4
    for (int ks = 0; ks < 16; ks++) {
        const uint32_t ko = (uint32_t)(ks * 32);
        uint32_t a0[4], a1[4];
        ldsm4(a0, aX + ko);
        ldsm4(a1, aX + 16 * LST + ko);
#pragma unroll
        for (int t = 0; t < 4; t++) {
            uint32_t bh[4];
            ldsm4(bh, bW + (uint32_t)(t * 16) * LST + ko);
            mma_f16(acc[0][t * 2], a0, bh[0], bh[1]);
            mma_f16(acc[0][t * 2 + 1], a0, bh[2], bh[3]);
            mma_f16(acc[1][t * 2], a1, bh[0], bh[1]);
            mma_f16(acc[1][t * 2 + 1], a1, bh[2], bh[3]);
        }
    }

    // epilogue: + bias, write
#pragma unroll
    for (int mf = 0; mf < 2; mf++)
#pragma unroll
        for (int j = 0; j < 8; j++) {
            const float* c = acc[mf][j];
            int m = row0 + mw * 32 + mf * 16 + rr4;
            int col = nw * 64 + (j >> 1) * 16 + (j & 1) * 8 + cc2;
            float b0 = bias[col], b1 = bias[col + 1];
            if (which == 2) {
                // transposed fp16 write: vtf[col][token]
                vtf[(size_t)col * NROWS + m]           = __float2half(c[0] + b0);
                vtf[(size_t)(col + 1) * NROWS + m]     = __float2half(c[1] + b1);
                vtf[(size_t)col * NROWS + m + 8]       = __float2half(c[2] + b0);
                vtf[(size_t)(col + 1) * NROWS + m + 8] = __float2half(c[3] + b1);
            } else {
                __half* dst = which == 0 ? qf : kf;
                *(uint32_t*)(dst + (size_t)m * HID + col) = h2pack(c[0] + b0, c[1] + b1);
                *(uint32_t*)(dst + (size_t)(m + 8) * HID + col) = h2pack(c[2] + b0, c[3] + b1);
            }
        }
}

// ---------------- warp-specialized HMMA attention (j-split x8, P ring x4) ----
#define STQ 528
#define STP 144
#define STV 144
#define Q_O    0
#define K_O    33792
#define KBUF   33792
#define V_O    101376
#define VBUF   36864
#define P_O    175104
#define PBUF   9216
#define PDEPTH 4
#define SMEMB  (P_O + PDEPTH * PBUF)   // 211968

__device__ __forceinline__ void stageK_async(uint32_t sb, int off, const __half* src,
                                             int r0, int t) {
    for (int f = t; f < 2048; f += 256) {
        int row = f >> 5, u = f & 31;
        cpasync16(sb + off + row * STQ + u * 16, src + (size_t)(r0 + row) * HID + u * 8);
    }
}
__device__ __forceinline__ void stageVt_async(uint32_t sb, int off, const __half* src,
                                              int j0, int t) {
    for (int f = t; f < 2048; f += 256) {
        int row = f >> 3, u = f & 7;
        cpasync16(sb + off + row * STV + u * 16, src + (size_t)row * NROWS + j0 + u * 8);
    }
}

__global__ __launch_bounds__(512)
void attn_kernel(float* __restrict__ out)
{
    extern __shared__ __align__(128) char smem[];
    const uint32_t sb = smem_to_u32(smem);
    const int tid = threadIdx.x, wid = tid >> 5, lane = tid & 31;
    const int t256 = tid & 255;
    const int w = wid & 7;
    const int mw = w & 1, nw = w >> 1;
    const int row0 = blockIdx.x * 64;
    const int jbase = blockIdx.y * (NROWS / JSPLIT);
    const int g = lane >> 3, rr = lane & 7;
    const int rr4 = lane >> 2, cc2 = (lane & 3) * 2;

    const uint32_t loA_Q = (uint32_t)((rr + (g & 1) * 8) * STQ + (g >> 1) * 16);
    const uint32_t loA_P = (uint32_t)((rr + (g & 1) * 8) * STP + (g >> 1) * 16);
    const uint32_t loB_K = (uint32_t)((rr + (g >> 1) * 8) * STQ + (g & 1) * 16);
    const uint32_t loB_V = (uint32_t)((rr + (g >> 1) * 8) * STV + (g & 1) * 16);

    if (wid < 8) {
        // ============ group A: MMA1 + sigmoid -> P ring ============
        stageK_async(sb, Q_O, g_qf, row0, t256);
        stageK_async(sb, K_O, g_kf, jbase, t256);
        CP_COMMIT();

        const uint32_t aQ  = sb + Q_O + (uint32_t)(mw * 32) * STQ + loA_Q;
        const uint32_t bKb = sb + K_O + (uint32_t)(nw * 16) * STQ + loB_K;

        for (int i = 0; i < NCHSEG; i++) {
            CP_WAIT(0);
            BAR_SYNC(1, 256);
            if (i + 1 < NCHSEG) {
                stageK_async(sb, K_O + ((i + 1) & 1) * KBUF, g_kf, jbase + (i + 1) * BJ, t256);
                CP_COMMIT();
            }

            float s[2][2][4];
#pragma unroll
            for (int a = 0; a < 2; a++)
#pragma unroll
                for (int b = 0; b < 2; b++)
#pragma unroll
                    for (int c = 0; c < 4; c++) s[a][b][c] = 0.0f;

            const uint32_t bK = bKb + (uint32_t)((i & 1) * KBUF);
#pragma unroll 8
            for (int ks = 0; ks < 16; ks++) {
                const uint32_t ko = (uint32_t)(ks * 32);
                uint32_t a0[4], a1[4], bh[4];
                ldsm4(a0, aQ + ko);
                ldsm4(a1, aQ + 16 * STQ + ko);
                ldsm4(bh, bK + ko);
                mma_f16(s[0][0], a0, bh[0], bh[1]); mma_f16(s[0][1], a0, bh[2], bh[3]);
                mma_f16(s[1][0], a1, bh[0], bh[1]); mma_f16(s[1][1], a1, bh[2], bh[3]);
            }

            uint32_t pk[2][2][2];
#pragma unroll
            for (int mf = 0; mf < 2; mf++)
#pragma unroll
                for (int nf = 0; nf < 2; nf++) {
                    const float* c = s[mf][nf];
                    pk[mf][nf][0] = h2pack(fsig(c[0]), fsig(c[1]));
                    pk[mf][nf][1] = h2pack(fsig(c[2]), fsig(c[3]));
                }

            if (i >= PDEPTH) BAR_SYNC(7 + (i & 3), 512);   // P[i&3] drained
            const uint32_t Pb = (uint32_t)(P_O + (i & 3) * PBUF);
#pragma unroll
            for (int mf = 0; mf < 2; mf++)
#pragma unroll
                for (int nf = 0; nf < 2; nf++) {
                    int m = mw * 32 + mf * 16 + rr4;
                    int n = nw * 16 + nf * 8 + cc2;
                    *(uint32_t*)(smem + Pb + m * STP + n * 2) = pk[mf][nf][0];
                    *(uint32_t*)(smem + Pb + (m + 8) * STP + n * 2) = pk[mf][nf][1];
                }
            __threadfence_block();
            BAR_ARRIVE(3 + (i & 3), 512);                  // P[i&3] full
        }
    } else {
        // ============ group B: MMA2 ============
        stageVt_async(sb, V_O, g_vtf, jbase, t256);
        CP_COMMIT();

        float oacc[2][8][4];
#pragma unroll
        for (int a = 0; a < 2; a++)
#pragma unroll
            for (int b = 0; b < 8; b++)
#pragma unroll
                for (int c = 0; c < 4; c++) oacc[a][b][c] = 0.0f;

        const uint32_t aPb = sb + P_O + (uint32_t)(mw * 32) * STP + loA_P;
        const uint32_t bVb = sb + V_O + (uint32_t)(nw * 64) * STV + loB_V;

        for (int i = 0; i < NCHSEG; i++) {
            BAR_SYNC(3 + (i & 3), 512);                    // P[i&3] full
            CP_WAIT(0);
            BAR_SYNC(2, 256);                              // V[i&1] visible
            if (i + 1 < NCHSEG) {
                stageVt_async(sb, V_O + ((i + 1) & 1) * VBUF, g_vtf, jbase + (i + 1) * BJ, t256);
                CP_COMMIT();
            }

            const uint32_t aP = aPb + (uint32_t)((i & 3) * PBUF);
            const uint32_t bV = bVb + (uint32_t)((i & 1) * VBUF);
#pragma unroll
            for (int ks = 0; ks < 4; ks++) {
                const uint32_t ko = (uint32_t)(ks * 32);
                uint32_t p0[4], p1[4];
                ldsm4(p0, aP + ko);
                ldsm4(p1, aP + 16 * STP + ko);
#pragma unroll
                for (int t = 0; t < 4; t++) {
                    uint32_t bh[4];
                    ldsm4(bh, bV + (uint32_t)(t * 16) * STV + ko);
                    mma_f16(oacc[0][t * 2], p0, bh[0], bh[1]);
                    mma_f16(oacc[0][t * 2 + 1], p0, bh[2], bh[3]);
                    mma_f16(oacc[1][t * 2], p1, bh[0], bh[1]);
                    mma_f16(oacc[1][t * 2 + 1], p1, bh[2], bh[3]);
                }
            }
            BAR_ARRIVE(7 + (i & 3), 512);                  // P[i&3] empty
        }

        // epilogue: jseg 0 -> fp32 out ; jseg 1..7 -> fp16 partial
        if (blockIdx.y == 0) {
#pragma unroll
            for (int mf = 0; mf < 2; mf++)
#pragma unroll
                for (int j = 0; j < 8; j++) {
                    const float* c = oacc[mf][j];
                    int m = row0 + mw * 32 + mf * 16 + rr4;
                    int col = nw * 64 + (j >> 1) * 16 + (j & 1) * 8 + cc2;
                    *(float2*)(out + (size_t)m * HID + col) = make_float2(c[0], c[1]);
                    *(float2*)(out + (size_t)(m + 8) * HID + col) = make_float2(c[2], c[3]);
                }
        } else {
            __half* php = g_ph + (size_t)(blockIdx.y - 1) * NROWS * HID;
#pragma unroll
            for (int mf = 0; mf < 2; mf++)
#pragma unroll
                for (int j = 0; j < 8; j++) {
                    const float* c = oacc[mf][j];
                    int m = row0 + mw * 32 + mf * 16 + rr4;
                    int col = nw * 64 + (j >> 1) * 16 + (j & 1) * 8 + cc2;
                    *(uint32_t*)(php + (size_t)m * HID + col) = h2pack(c[0], c[1]);
                    *(uint32_t*)(php + (size_t)(m + 8) * HID + col) = h2pack(c[2], c[3]);
                }
        }
    }
}

// ---------------- deterministic reduce of fp16 partials ----------------
__global__ __launch_bounds__(NTHREADS)
void reduce_kernel(float* __restrict__ out)
{
    size_t i = ((size_t)blockIdx.x * NTHREADS + threadIdx.x) * 4;
    float4 a = *(float4*)(out + i);
#pragma unroll
    for (int s = 0; s < JSPLIT - 1; s++) {
        uint2 b = *(const uint2*)(g_ph + (size_t)s * NROWS * HID + i);
        __half2 h0 = *(__half2*)&b.x, h1 = *(__half2*)&b.y;
        float2 f0 = __half22float2(h0), f1 = __half22float2(h1);
        a.x += f0.x; a.y += f0.y; a.z += f1.x; a.w += f1.y;
    }
    *(float4*)(out + i) = a;
}

// ---------------------------------------------------------------------------
extern "C" void kernel_launch(void* const* d_in, const int* in_sizes, int n_in,
                              void* d_out, int out_size)
{
    const float* query = (const float*)d_in[0];
    const float* key_  = (const float*)d_in[1];
    const float* value = (const float*)d_in[2];
    const float* Wq = (const float*)d_in[3];
    const float* bq = (const float*)d_in[4];
    const float* Wk = (const float*)d_in[5];
    const float* bk = (const float*)d_in[6];
    const float* Wv = (const float*)d_in[7];
    const float* bv = (const float*)d_in[8];
    float* out = (float*)d_out;
    (void)in_sizes; (void)n_in; (void)out_size;

    __half *qf, *kf, *vtf;
    cudaGetSymbolAddress((void**)&qf, g_qf);
    cudaGetSymbolAddress((void**)&kf, g_kf);
    cudaGetSymbolAddress((void**)&vtf, g_vtf);

    cudaFuncSetAttribute(linear_hmma_kernel, cudaFuncAttributeMaxDynamicSharedMemorySize, LSMEMB);
    linear_hmma_kernel<<<dim3(NROWS / 64, 3), NTHREADS, LSMEMB>>>(
        query, key_, value, Wq, Wk, Wv, bq, bk, bv, qf, kf, vtf);

    cudaFuncSetAttribute(attn_kernel, cudaFuncAttributeMaxDynamicSharedMemorySize, SMEMB);
    attn_kernel<<<dim3(NROWS / 64, JSPLIT), 512, SMEMB>>>(out);

    reduce_kernel<<<NROWS * HID / 4 / NTHREADS, NTHREADS>>>(out);
}

// round 11
// speedup vs baseline: 9.6704x; 1.0138x over previous
#include <cuda_runtime.h>
#include <cuda_bf16.h>
#include <cuda_fp16.h>
#include <cstdint>

#define NROWS 8192
#define HID   256
#define NTHREADS 256
#define BJ 64
#define JSPLIT 8
#define NCHSEG (NROWS / BJ / JSPLIT)   // 16 chunks per CTA

// ---------------- device scratch ----------------
__device__ __half g_qf[NROWS * HID];
__device__ __half g_kf[NROWS * HID];
__device__ __half g_vtf[HID * NROWS];                  // [hid][token] fp16
__device__ __half g_ph[(JSPLIT - 1) * NROWS * HID];    // fp16 partial O, jseg 1..7

// sigmoid via HW tanh
__device__ __forceinline__ float fsig(float x) {
    float t; asm("tanh.approx.f32 %0, %1;" : "=f"(t) : "f"(x * 0.5f));
    return fmaf(0.5f, t, 0.5f);
}
__device__ __forceinline__ uint32_t h2pack(float a, float b) {
    __half2 h = __floats2half2_rn(a, b);
    return *(uint32_t*)&h;
}
__device__ __forceinline__ uint32_t smem_to_u32(const void* p) {
    uint32_t a;
    asm("{ .reg .u64 t; cvta.to.shared.u64 t, %1; cvt.u32.u64 %0, t; }" : "=r"(a) : "l"(p));
    return a;
}
__device__ __forceinline__ void ldsm4(uint32_t r[4], uint32_t addr) {
    asm volatile("ldmatrix.sync.aligned.m8n8.x4.shared.b16 {%0,%1,%2,%3}, [%4];"
                 : "=r"(r[0]), "=r"(r[1]), "=r"(r[2]), "=r"(r[3]) : "r"(addr));
}
__device__ __forceinline__ void mma_f16(float c[4], const uint32_t a[4], uint32_t b0, uint32_t b1) {
    asm volatile("mma.sync.aligned.m16n8k16.row.col.f32.f16.f16.f32 "
                 "{%0,%1,%2,%3}, {%4,%5,%6,%7}, {%8,%9}, {%0,%1,%2,%3};"
                 : "+f"(c[0]), "+f"(c[1]), "+f"(c[2]), "+f"(c[3])
                 : "r"(a[0]), "r"(a[1]), "r"(a[2]), "r"(a[3]), "r"(b0), "r"(b1));
}
__device__ __forceinline__ void cpasync16(uint32_t saddr, const void* g) {
    asm volatile("cp.async.cg.shared.global [%0], [%1], 16;" :: "r"(saddr), "l"(g));
}
#define CP_COMMIT() asm volatile("cp.async.commit_group;" ::: "memory")
#define CP_WAIT(N)  asm volatile("cp.async.wait_group %0;" :: "n"(N) : "memory")
#define BAR_SYNC(id, cnt)   asm volatile("bar.sync %0, %1;"   :: "r"(id), "n"(cnt) : "memory")
#define BAR_ARRIVE(id, cnt) asm volatile("bar.arrive %0, %1;" :: "r"(id), "n"(cnt) : "memory")

// ================= HMMA linear: out = X @ W^T + b =================
// grid (128, 3): y=0 -> Q (fp16), y=1 -> K (fp16), y=2 -> V^T (fp16, [hid][token])
// V^T path: mma -> smem transpose (reuse X region) -> coalesced 16B stores.
#define LST 528
#define LX_O 0
#define LW_O 33792
#define LSMEMB 168960

__global__ __launch_bounds__(NTHREADS)
void linear_hmma_kernel(const float* __restrict__ Xq, const float* __restrict__ Xk,
                        const float* __restrict__ Xv,
                        const float* __restrict__ Wq, const float* __restrict__ Wk,
                        const float* __restrict__ Wv,
                        const float* __restrict__ bq, const float* __restrict__ bk,
                        const float* __restrict__ bv,
                        __half* __restrict__ qf, __half* __restrict__ kf,
                        __half* __restrict__ vtf)
{
    extern __shared__ __align__(128) char smem[];
    const uint32_t sb = smem_to_u32(smem);
    const int tid = threadIdx.x, warp = tid >> 5, lane = tid & 31;
    const int mw = warp & 1, nw = warp >> 1;
    const int row0 = blockIdx.x * 64;
    const int which = blockIdx.y;
    const int g = lane >> 3, rr = lane & 7;
    const int rr4 = lane >> 2, cc2 = (lane & 3) * 2;

    const float* X = which == 0 ? Xq : (which == 1 ? Xk : Xv);
    const float* W = which == 0 ? Wq : (which == 1 ? Wk : Wv);
    const float* bias = which == 0 ? bq : (which == 1 ? bk : bv);

    // stage X tile (64x256) fp32 -> fp16 smem
    for (int f = tid; f < 4096; f += NTHREADS) {
        int row = f >> 6, c4 = (f & 63) << 2;
        float4 v = *(const float4*)(X + (size_t)(row0 + row) * HID + c4);
        *(uint2*)(smem + LX_O + row * LST + c4 * 2) =
            make_uint2(h2pack(v.x, v.y), h2pack(v.z, v.w));
    }
    // stage W (256x256) fp32 -> fp16 smem
    for (int f = tid; f < 16384; f += NTHREADS) {
        int row = f >> 6, c4 = (f & 63) << 2;
        float4 v = *(const float4*)(W + (size_t)row * HID + c4);
        *(uint2*)(smem + LW_O + row * LST + c4 * 2) =
            make_uint2(h2pack(v.x, v.y), h2pack(v.z, v.w));
    }
    __syncthreads();

    const uint32_t loA = (uint32_t)((rr + (g & 1) * 8) * LST + (g >> 1) * 16);
    const uint32_t loB = (uint32_t)((rr + (g >> 1) * 8) * LST + (g & 1) * 16);
    const uint32_t aX = sb + LX_O + (uint32_t)(mw * 32) * LST + loA;
    const uint32_t bW = sb + LW_O + (uint32_t)(nw * 64) * LST + loB;

    float acc[2][8][4];
#pragma unroll
    for (int a = 0; a < 2; a++)
#pragma unroll
        for (int b = 0; b < 8; b++)
#pragma unroll
            for (int c = 0; c < 4; c++) acc[a][b][c] = 0.0f;

#pragma unroll 4
    for (int ks = 0; ks < 16; ks++) {
        const uint32_t ko = (uint32_t)(ks * 32);
        uint32_t a0[4], a1[4];
        ldsm4(a0, aX + ko);
        ldsm4(a1, aX + 16 * LST + ko);
#pragma unroll
        for (int t = 0; t < 4; t++) {
            uint32_t bh[4];
            ldsm4(bh, bW + (uint32_t)(t * 16) * LST + ko);
            mma_f16(acc[0][t * 2], a0, bh[0], bh[1]);
            mma_f16(acc[0][t * 2 + 1], a0, bh[2], bh[3]);
            mma_f16(acc[1][t * 2], a1, bh[0], bh[1]);
            mma_f16(acc[1][t * 2 + 1], a1, bh[2], bh[3]);
        }
    }

    if (which == 2) {
        // V^T: transpose via smem (reuse X region: 256 hid-rows x 128B), then
        // coalesced stores to g_vtf[hid][token].
        __syncthreads();   // all warps done reading sX
#pragma unroll
        for (int mf = 0; mf < 2; mf++)
#pragma unroll
            for (int j = 0; j < 8; j++) {
                const float* c = acc[mf][j];
                int ml = mw * 32 + mf * 16 + rr4;           // local token 0..63
                int col = nw * 64 + (j >> 1) * 16 + (j & 1) * 8 + cc2;
                float b0 = bias[col], b1 = bias[col + 1];
                *(__half*)(smem + col * 128 + ml * 2)             = __float2half(c[0] + b0);
                *(__half*)(smem + (col + 1) * 128 + ml * 2)       = __float2half(c[1] + b1);
                *(__half*)(smem + col * 128 + (ml + 8) * 2)       = __float2half(c[2] + b0);
                *(__half*)(smem + (col + 1) * 128 + (ml + 8) * 2) = __float2half(c[3] + b1);
            }
        __syncthreads();
        for (int f = tid; f < 2048; f += NTHREADS) {
            int row = f >> 3, u = f & 7;                    // hid row, 16B chunk
            *(uint4*)(vtf + (size_t)row * NROWS + row0 + u * 8) =
                *(const uint4*)(smem + row * 128 + u * 16);
        }
    } else {
        __half* dst = which == 0 ? qf : kf;
#pragma unroll
        for (int mf = 0; mf < 2; mf++)
#pragma unroll
            for (int j = 0; j < 8; j++) {
                const float* c = acc[mf][j];
                int m = row0 + mw * 32 + mf * 16 + rr4;
                int col = nw * 64 + (j >> 1) * 16 + (j & 1) * 8 + cc2;
                float b0 = bias[col], b1 = bias[col + 1];
                *(uint32_t*)(dst + (size_t)m * HID + col) = h2pack(c[0] + b0, c[1] + b1);
                *(uint32_t*)(dst + (size_t)(m + 8) * HID + col) = h2pack(c[2] + b0, c[3] + b1);
            }
    }
}

// ---------------- warp-specialized HMMA attention (j-split x8, P ring x4) ----
#define STQ 528
#define STP 144
#define STV 144
#define Q_O    0
#define K_O    33792
#define KBUF   33792
#define V_O    101376
#define VBUF   36864
#define P_O    175104
#define PBUF   9216
#define PDEPTH 4
#define SMEMB  (P_O + PDEPTH * PBUF)   // 211968

__device__ __forceinline__ void stageK_async(uint32_t sb, int off, const __half* src,
                                             int r0, int t) {
    for (int f = t; f < 2048; f += 256) {
        int row = f >> 5, u = f & 31;
        cpasync16(sb + off + row * STQ + u * 16, src + (size_t)(r0 + row) * HID + u * 8);
    }
}
__device__ __forceinline__ void stageVt_async(uint32_t sb, int off, const __half* src,
                                              int j0, int t) {
    for (int f = t; f < 2048; f += 256) {
        int row = f >> 3, u = f & 7;
        cpasync16(sb + off + row * STV + u * 16, src + (size_t)row * NROWS + j0 + u * 8);
    }
}

__global__ __launch_bounds__(512)
void attn_kernel(float* __restrict__ out)
{
    extern __shared__ __align__(128) char smem[];
    const uint32_t sb = smem_to_u32(smem);
    const int tid = threadIdx.x, wid = tid >> 5, lane = tid & 31;
    const int t256 = tid & 255;
    const int w = wid & 7;
    const int mw = w & 1, nw = w >> 1;
    const int row0 = blockIdx.x * 64;
    const int jbase = blockIdx.y * (NROWS / JSPLIT);
    const int g = lane >> 3, rr = lane & 7;
    const int rr4 = lane >> 2, cc2 = (lane & 3) * 2;

    const uint32_t loA_Q = (uint32_t)((rr + (g & 1) * 8) * STQ + (g >> 1) * 16);
    const uint32_t loA_P = (uint32_t)((rr + (g & 1) * 8) * STP + (g >> 1) * 16);
    const uint32_t loB_K = (uint32_t)((rr + (g >> 1) * 8) * STQ + (g & 1) * 16);
    const uint32_t loB_V = (uint32_t)((rr + (g >> 1) * 8) * STV + (g & 1) * 16);

    if (wid < 8) {
        // ============ group A: MMA1 + sigmoid -> P ring ============
        stageK_async(sb, Q_O, g_qf, row0, t256);
        stageK_async(sb, K_O, g_kf, jbase, t256);
        CP_COMMIT();

        const uint32_t aQ  = sb + Q_O + (uint32_t)(mw * 32) * STQ + loA_Q;
        const uint32_t bKb = sb + K_O + (uint32_t)(nw * 16) * STQ + loB_K;

        for (int i = 0; i < NCHSEG; i++) {
            CP_WAIT(0);
            BAR_SYNC(1, 256);
            if (i + 1 < NCHSEG) {
                stageK_async(sb, K_O + ((i + 1) & 1) * KBUF, g_kf, jbase + (i + 1) * BJ, t256);
                CP_COMMIT();
            }

            float s[2][2][4];
#pragma unroll
            for (int a = 0; a < 2; a++)
#pragma unroll
                for (int b = 0; b < 2; b++)
#pragma unroll
                    for (int c = 0; c < 4; c++) s[a][b][c] = 0.0f;

            const uint32_t bK = bKb + (uint32_t)((i & 1) * KBUF);
#pragma unroll 8
            for (int ks = 0; ks < 16; ks++) {
                const uint32_t ko = (uint32_t)(ks * 32);
                uint32_t a0[4], a1[4], bh[4];
                ldsm4(a0, aQ + ko);
                ldsm4(a1, aQ + 16 * STQ + ko);
                ldsm4(bh, bK + ko);
                mma_f16(s[0][0], a0, bh[0], bh[1]); mma_f16(s[0][1], a0, bh[2], bh[3]);
                mma_f16(s[1][0], a1, bh[0], bh[1]); mma_f16(s[1][1], a1, bh[2], bh[3]);
            }

            uint32_t pk[2][2][2];
#pragma unroll
            for (int mf = 0; mf < 2; mf++)
#pragma unroll
                for (int nf = 0; nf < 2; nf++) {
                    const float* c = s[mf][nf];
                    pk[mf][nf][0] = h2pack(fsig(c[0]), fsig(c[1]));
                    pk[mf][nf][1] = h2pack(fsig(c[2]), fsig(c[3]));
                }

            if (i >= PDEPTH) BAR_SYNC(7 + (i & 3), 512);   // P[i&3] drained
            const uint32_t Pb = (uint32_t)(P_O + (i & 3) * PBUF);
#pragma unroll
            for (int mf = 0; mf < 2; mf++)
#pragma unroll
                for (int nf = 0; nf < 2; nf++) {
                    int m = mw * 32 + mf * 16 + rr4;
                    int n = nw * 16 + nf * 8 + cc2;
                    *(uint32_t*)(smem + Pb + m * STP + n * 2) = pk[mf][nf][0];
                    *(uint32_t*)(smem + Pb + (m + 8) * STP + n * 2) = pk[mf][nf][1];
                }
            __threadfence_block();
            BAR_ARRIVE(3 + (i & 3), 512);                  // P[i&3] full
        }
    } else {
        // ============ group B: MMA2 ============
        stageVt_async(sb, V_O, g_vtf, jbase, t256);
        CP_COMMIT();

        float oacc[2][8][4];
#pragma unroll
        for (int a = 0; a < 2; a++)
#pragma unroll
            for (int b = 0; b < 8; b++)
#pragma unroll
                for (int c = 0; c < 4; c++) oacc[a][b][c] = 0.0f;

        const uint32_t aPb = sb + P_O + (uint32_t)(mw * 32) * STP + loA_P;
        const uint32_t bVb = sb + V_O + (uint32_t)(nw * 64) * STV + loB_V;

        for (int i = 0; i < NCHSEG; i++) {
            BAR_SYNC(3 + (i & 3), 512);                    // P[i&3] full
            CP_WAIT(0);
            BAR_SYNC(2, 256);                              // V[i&1] visible
            if (i + 1 < NCHSEG) {
                stageVt_async(sb, V_O + ((i + 1) & 1) * VBUF, g_vtf, jbase + (i + 1) * BJ, t256);
                CP_COMMIT();
            }

            const uint32_t aP = aPb + (uint32_t)((i & 3) * PBUF);
            const uint32_t bV = bVb + (uint32_t)((i & 1) * VBUF);
#pragma unroll
            for (int ks = 0; ks < 4; ks++) {
                const uint32_t ko = (uint32_t)(ks * 32);
                uint32_t p0[4], p1[4];
                ldsm4(p0, aP + ko);
                ldsm4(p1, aP + 16 * STP + ko);
#pragma unroll
                for (int t = 0; t < 4; t++) {
                    uint32_t bh[4];
                    ldsm4(bh, bV + (uint32_t)(t * 16) * STV + ko);
                    mma_f16(oacc[0][t * 2], p0, bh[0], bh[1]);
                    mma_f16(oacc[0][t * 2 + 1], p0, bh[2], bh[3]);
                    mma_f16(oacc[1][t * 2], p1, bh[0], bh[1]);
                    mma_f16(oacc[1][t * 2 + 1], p1, bh[2], bh[3]);
                }
            }
            BAR_ARRIVE(7 + (i & 3), 512);                  // P[i&3] empty
        }

        // epilogue: jseg 0 -> fp32 out ; jseg 1..7 -> fp16 partial
        if (blockIdx.y == 0) {
#pragma unroll
            for (int mf = 0; mf < 2; mf++)
#pragma unroll
                for (int j = 0; j < 8; j++) {
                    const float* c = oacc[mf][j];
                    int m = row0 + mw * 32 + mf * 16 + rr4;
                    int col = nw * 64 + (j >> 1) * 16 + (j & 1) * 8 + cc2;
                    *(float2*)(out + (size_t)m * HID + col) = make_float2(c[0], c[1]);
                    *(float2*)(out + (size_t)(m + 8) * HID + col) = make_float2(c[2], c[3]);
                }
        } else {
            __half* php = g_ph + (size_t)(blockIdx.y - 1) * NROWS * HID;
#pragma unroll
            for (int mf = 0; mf < 2; mf++)
#pragma unroll
                for (int j = 0; j < 8; j++) {
                    const float* c = oacc[mf][j];
                    int m = row0 + mw * 32 + mf * 16 + rr4;
                    int col = nw * 64 + (j >> 1) * 16 + (j & 1) * 8 + cc2;
                    *(uint32_t*)(php + (size_t)m * HID + col) = h2pack(c[0], c[1]);
                    *(uint32_t*)(php + (size_t)(m + 8) * HID + col) = h2pack(c[2], c[3]);
                }
        }
    }
}

// ---------------- deterministic reduce of fp16 partials ----------------
__global__ __launch_bounds__(NTHREADS)
void reduce_kernel(float* __restrict__ out)
{
    size_t i = ((size_t)blockIdx.x * NTHREADS + threadIdx.x) * 4;
    float4 a = *(float4*)(out + i);
#pragma unroll
    for (int s = 0; s < JSPLIT - 1; s++) {
        uint2 b = *(const uint2*)(g_ph + (size_t)s * NROWS * HID + i);
        __half2 h0 = *(__half2*)&b.x, h1 = *(__half2*)&b.y;
        float2 f0 = __half22float2(h0), f1 = __half22float2(h1);
        a.x += f0.x; a.y += f0.y; a.z += f1.x; a.w += f1.y;
    }
    *(float4*)(out + i) = a;
}

// ---------------------------------------------------------------------------
extern "C" void kernel_launch(void* const* d_in, const int* in_sizes, int n_in,
                              void* d_out, int out_size)
{
    const float* query = (const float*)d_in[0];
    const float* key_  = (const float*)d_in[1];
    const float* value = (const float*)d_in[2];
    const float* Wq = (const float*)d_in[3];
    const float* bq = (const float*)d_in[4];
    const float* Wk = (const float*)d_in[5];
    const float* bk = (const float*)d_in[6];
    const float* Wv = (const float*)d_in[7];
    const float* bv = (const float*)d_in[8];
    float* out = (float*)d_out;
    (void)in_sizes; (void)n_in; (void)out_size;

    __half *qf, *kf, *vtf;
    cudaGetSymbolAddress((void**)&qf, g_qf);
    cudaGetSymbolAddress((void**)&kf, g_kf);
    cudaGetSymbolAddress((void**)&vtf, g_vtf);

    cudaFuncSetAttribute(linear_hmma_kernel, cudaFuncAttributeMaxDynamicSharedMemorySize, LSMEMB);
    linear_hmma_kernel<<<dim3(NROWS / 64, 3), NTHREADS, LSMEMB>>>(
        query, key_, value, Wq, Wk, Wv, bq, bk, bv, qf, kf, vtf);

    cudaFuncSetAttribute(attn_kernel, cudaFuncAttributeMaxDynamicSharedMemorySize, SMEMB);
    attn_kernel<<<dim3(NROWS / 64, JSPLIT), 512, SMEMB>>>(out);

    reduce_kernel<<<NROWS * HID / 4 / NTHREADS, NTHREADS>>>(out);
}

// round 12
// speedup vs baseline: 10.0091x; 1.0350x over previous
#include <cuda_runtime.h>
#include <cuda_bf16.h>
#include <cuda_fp16.h>
#include <cstdint>

#define NROWS 8192
#define HID   256
#define NTHREADS 256
#define BJ 64
#define JSPLIT 8
#define NCHSEG (NROWS / BJ / JSPLIT)   // 16 chunks per CTA

// ---------------- device scratch ----------------
__device__ __half g_qf[NROWS * HID];
__device__ __half g_kf[NROWS * HID];
__device__ __half g_vtf[HID * NROWS];                  // [hid][token] fp16
__device__ __half g_ph[(JSPLIT - 1) * NROWS * HID];    // fp16 partial O, jseg 1..7
__device__ __half g_w16[3 * HID * HID];                // fp16 Wq|Wk|Wv

// sigmoid via HW tanh
__device__ __forceinline__ float fsig(float x) {
    float t; asm("tanh.approx.f32 %0, %1;" : "=f"(t) : "f"(x * 0.5f));
    return fmaf(0.5f, t, 0.5f);
}
__device__ __forceinline__ uint32_t h2pack(float a, float b) {
    __half2 h = __floats2half2_rn(a, b);
    return *(uint32_t*)&h;
}
__device__ __forceinline__ uint32_t smem_to_u32(const void* p) {
    uint32_t a;
    asm("{ .reg .u64 t; cvta.to.shared.u64 t, %1; cvt.u32.u64 %0, t; }" : "=r"(a) : "l"(p));
    return a;
}
__device__ __forceinline__ void ldsm4(uint32_t r[4], uint32_t addr) {
    asm volatile("ldmatrix.sync.aligned.m8n8.x4.shared.b16 {%0,%1,%2,%3}, [%4];"
                 : "=r"(r[0]), "=r"(r[1]), "=r"(r[2]), "=r"(r[3]) : "r"(addr));
}
__device__ __forceinline__ void mma_f16(float c[4], const uint32_t a[4], uint32_t b0, uint32_t b1) {
    asm volatile("mma.sync.aligned.m16n8k16.row.col.f32.f16.f16.f32 "
                 "{%0,%1,%2,%3}, {%4,%5,%6,%7}, {%8,%9}, {%0,%1,%2,%3};"
                 : "+f"(c[0]), "+f"(c[1]), "+f"(c[2]), "+f"(c[3])
                 : "r"(a[0]), "r"(a[1]), "r"(a[2]), "r"(a[3]), "r"(b0), "r"(b1));
}
__device__ __forceinline__ void cpasync16(uint32_t saddr, const void* g) {
    asm volatile("cp.async.cg.shared.global [%0], [%1], 16;" :: "r"(saddr), "l"(g));
}
#define CP_COMMIT() asm volatile("cp.async.commit_group;" ::: "memory")
#define CP_WAIT(N)  asm volatile("cp.async.wait_group %0;" :: "n"(N) : "memory")
#define BAR_SYNC(id, cnt)   asm volatile("bar.sync %0, %1;"   :: "r"(id), "n"(cnt) : "memory")
#define BAR_ARRIVE(id, cnt) asm volatile("bar.arrive %0, %1;" :: "r"(id), "n"(cnt) : "memory")

// ---------------- W fp32 -> fp16 (once) ----------------
__global__ __launch_bounds__(NTHREADS)
void wconv_kernel(const float* __restrict__ Wq, const float* __restrict__ Wk,
                  const float* __restrict__ Wv)
{
    const float* W = blockIdx.y == 0 ? Wq : (blockIdx.y == 1 ? Wk : Wv);
    __half* dst = g_w16 + (size_t)blockIdx.y * HID * HID;
    int i = (blockIdx.x * NTHREADS + threadIdx.x) * 4;
    float4 v = *(const float4*)(W + i);
    *(uint2*)(dst + i) = make_uint2(h2pack(v.x, v.y), h2pack(v.z, v.w));
}

// ================= HMMA linear: out = X @ W^T + b (512 threads) =============
// grid (128, 3): y=0 -> Q (fp16), y=1 -> K (fp16), y=2 -> V^T (fp16, [hid][token])
// W staged fp16 via cp.async (pre-converted); X converted in-kernel (overlapped).
#define LST 528
#define LX_O 0
#define LW_O 33792
#define LSMEMB 168960

__global__ __launch_bounds__(512)
void linear_hmma_kernel(const float* __restrict__ Xq, const float* __restrict__ Xk,
                        const float* __restrict__ Xv,
                        const float* __restrict__ bq, const float* __restrict__ bk,
                        const float* __restrict__ bv,
                        __half* __restrict__ qf, __half* __restrict__ kf,
                        __half* __restrict__ vtf)
{
    extern __shared__ __align__(128) char smem[];
    const uint32_t sb = smem_to_u32(smem);
    const int tid = threadIdx.x, wid = tid >> 5, lane = tid & 31;
    const int mw = wid & 1, nw = wid >> 1;          // M half (32) x N eighth (32)
    const int row0 = blockIdx.x * 64;
    const int which = blockIdx.y;
    const int g = lane >> 3, rr = lane & 7;
    const int rr4 = lane >> 2, cc2 = (lane & 3) * 2;

    const float* X = which == 0 ? Xq : (which == 1 ? Xk : Xv);
    const __half* w16 = g_w16 + (size_t)which * HID * HID;
    const float* bias = which == 0 ? bq : (which == 1 ? bk : bv);

    // W (256x256 fp16) -> smem via cp.async, 16B chunks
    for (int f = tid; f < 8192; f += 512) {
        int row = f >> 5, u = f & 31;
        cpasync16(sb + LW_O + row * LST + u * 16, w16 + (size_t)row * HID + u * 8);
    }
    CP_COMMIT();
    // X tile (64x256) fp32 -> fp16 smem (overlaps with W copies)
    for (int f = tid; f < 4096; f += 512) {
        int row = f >> 6, c4 = (f & 63) << 2;
        float4 v = *(const float4*)(X + (size_t)(row0 + row) * HID + c4);
        *(uint2*)(smem + LX_O + row * LST + c4 * 2) =
            make_uint2(h2pack(v.x, v.y), h2pack(v.z, v.w));
    }
    CP_WAIT(0);
    __syncthreads();

    const uint32_t loA = (uint32_t)((rr + (g & 1) * 8) * LST + (g >> 1) * 16);
    const uint32_t loB = (uint32_t)((rr + (g >> 1) * 8) * LST + (g & 1) * 16);
    const uint32_t aX = sb + LX_O + (uint32_t)(mw * 32) * LST + loA;
    const uint32_t bW = sb + LW_O + (uint32_t)(nw * 32) * LST + loB;

    float acc[2][4][4];
#pragma unroll
    for (int a = 0; a < 2; a++)
#pragma unroll
        for (int b = 0; b < 4; b++)
#pragma unroll
            for (int c = 0; c < 4; c++) acc[a][b][c] = 0.0f;

#pragma unroll 8
    for (int ks = 0; ks < 16; ks++) {
        const uint32_t ko = (uint32_t)(ks * 32);
        uint32_t a0[4], a1[4];
        ldsm4(a0, aX + ko);
        ldsm4(a1, aX + 16 * LST + ko);
#pragma unroll
        for (int t = 0; t < 2; t++) {
            uint32_t bh[4];
            ldsm4(bh, bW + (uint32_t)(t * 16) * LST + ko);
            mma_f16(acc[0][t * 2], a0, bh[0], bh[1]);
            mma_f16(acc[0][t * 2 + 1], a0, bh[2], bh[3]);
            mma_f16(acc[1][t * 2], a1, bh[0], bh[1]);
            mma_f16(acc[1][t * 2 + 1], a1, bh[2], bh[3]);
        }
    }

    if (which == 2) {
        // V^T: transpose via smem (reuse X region: 256 hid-rows x 128B), then
        // coalesced stores to g_vtf[hid][token].
        __syncthreads();   // all warps done reading sX
#pragma unroll
        for (int mf = 0; mf < 2; mf++)
#pragma unroll
            for (int j = 0; j < 4; j++) {
                const float* c = acc[mf][j];
                int ml = mw * 32 + mf * 16 + rr4;           // local token 0..63
                int col = nw * 32 + (j >> 1) * 16 + (j & 1) * 8 + cc2;
                float b0 = bias[col], b1 = bias[col + 1];
                *(__half*)(smem + col * 128 + ml * 2)             = __float2half(c[0] + b0);
                *(__half*)(smem + (col + 1) * 128 + ml * 2)       = __float2half(c[1] + b1);
                *(__half*)(smem + col * 128 + (ml + 8) * 2)       = __float2half(c[2] + b0);
                *(__half*)(smem + (col + 1) * 128 + (ml + 8) * 2) = __float2half(c[3] + b1);
            }
        __syncthreads();
        for (int f = tid; f < 2048; f += 512) {
            int row = f >> 3, u = f & 7;                    // hid row, 16B chunk
            *(uint4*)(vtf + (size_t)row * NROWS + row0 + u * 8) =
                *(const uint4*)(smem + row * 128 + u * 16);
        }
    } else {
        __half* dst = which == 0 ? qf : kf;
#pragma unroll
        for (int mf = 0; mf < 2; mf++)
#pragma unroll
            for (int j = 0; j < 4; j++) {
                const float* c = acc[mf][j];
                int m = row0 + mw * 32 + mf * 16 + rr4;
                int col = nw * 32 + (j >> 1) * 16 + (j & 1) * 8 + cc2;
                float b0 = bias[col], b1 = bias[col + 1];
                *(uint32_t*)(dst + (size_t)m * HID + col) = h2pack(c[0] + b0, c[1] + b1);
                *(uint32_t*)(dst + (size_t)(m + 8) * HID + col) = h2pack(c[2] + b0, c[3] + b1);
            }
    }
}

// ---------------- warp-specialized HMMA attention (j-split x8, P ring x4) ----
#define STQ 528
#define STP 144
#define STV 144
#define Q_O    0
#define K_O    33792
#define KBUF   33792
#define V_O    101376
#define VBUF   36864
#define P_O    175104
#define PBUF   9216
#define PDEPTH 4
#define SMEMB  (P_O + PDEPTH * PBUF)   // 211968

__device__ __forceinline__ void stageK_async(uint32_t sb, int off, const __half* src,
                                             int r0, int t) {
    for (int f = t; f < 2048; f += 256) {
        int row = f >> 5, u = f & 31;
        cpasync16(sb + off + row * STQ + u * 16, src + (size_t)(r0 + row) * HID + u * 8);
    }
}
__device__ __forceinline__ void stageVt_async(uint32_t sb, int off, const __half* src,
                                              int j0, int t) {
    for (int f = t; f < 2048; f += 256) {
        int row = f >> 3, u = f & 7;
        cpasync16(sb + off + row * STV + u * 16, src + (size_t)row * NROWS + j0 + u * 8);
    }
}

__global__ __launch_bounds__(512)
void attn_kernel(float* __restrict__ out)
{
    extern __shared__ __align__(128) char smem[];
    const uint32_t sb = smem_to_u32(smem);
    const int tid = threadIdx.x, wid = tid >> 5, lane = tid & 31;
    const int t256 = tid & 255;
    const int w = wid & 7;
    const int mw = w & 1, nw = w >> 1;
    const int row0 = blockIdx.x * 64;
    const int jbase = blockIdx.y * (NROWS / JSPLIT);
    const int g = lane >> 3, rr = lane & 7;
    const int rr4 = lane >> 2, cc2 = (lane & 3) * 2;

    const uint32_t loA_Q = (uint32_t)((rr + (g & 1) * 8) * STQ + (g >> 1) * 16);
    const uint32_t loA_P = (uint32_t)((rr + (g & 1) * 8) * STP + (g >> 1) * 16);
    const uint32_t loB_K = (uint32_t)((rr + (g >> 1) * 8) * STQ + (g & 1) * 16);
    const uint32_t loB_V = (uint32_t)((rr + (g >> 1) * 8) * STV + (g & 1) * 16);

    if (wid < 8) {
        // ============ group A: MMA1 + sigmoid -> P ring ============
        stageK_async(sb, Q_O, g_qf, row0, t256);
        stageK_async(sb, K_O, g_kf, jbase, t256);
        CP_COMMIT();

        const uint32_t aQ  = sb + Q_O + (uint32_t)(mw * 32) * STQ + loA_Q;
        const uint32_t bKb = sb + K_O + (uint32_t)(nw * 16) * STQ + loB_K;

        for (int i = 0; i < NCHSEG; i++) {
            CP_WAIT(0);
            BAR_SYNC(1, 256);
            if (i + 1 < NCHSEG) {
                stageK_async(sb, K_O + ((i + 1) & 1) * KBUF, g_kf, jbase + (i + 1) * BJ, t256);
                CP_COMMIT();
            }

            float s[2][2][4];
#pragma unroll
            for (int a = 0; a < 2; a++)
#pragma unroll
                for (int b = 0; b < 2; b++)
#pragma unroll
                    for (int c = 0; c < 4; c++) s[a][b][c] = 0.0f;

            const uint32_t bK = bKb + (uint32_t)((i & 1) * KBUF);
#pragma unroll 8
            for (int ks = 0; ks < 16; ks++) {
                const uint32_t ko = (uint32_t)(ks * 32);
                uint32_t a0[4], a1[4], bh[4];
                ldsm4(a0, aQ + ko);
                ldsm4(a1, aQ + 16 * STQ + ko);
                ldsm4(bh, bK + ko);
                mma_f16(s[0][0], a0, bh[0], bh[1]); mma_f16(s[0][1], a0, bh[2], bh[3]);
                mma_f16(s[1][0], a1, bh[0], bh[1]); mma_f16(s[1][1], a1, bh[2], bh[3]);
            }

            uint32_t pk[2][2][2];
#pragma unroll
            for (int mf = 0; mf < 2; mf++)
#pragma unroll
                for (int nf = 0; nf < 2; nf++) {
                    const float* c = s[mf][nf];
                    pk[mf][nf][0] = h2pack(fsig(c[0]), fsig(c[1]));
                    pk[mf][nf][1] = h2pack(fsig(c[2]), fsig(c[3]));
                }

            if (i >= PDEPTH) BAR_SYNC(7 + (i & 3), 512);   // P[i&3] drained
            const uint32_t Pb = (uint32_t)(P_O + (i & 3) * PBUF);
#pragma unroll
            for (int mf = 0; mf < 2; mf++)
#pragma unroll
                for (int nf = 0; nf < 2; nf++) {
                    int m = mw * 32 + mf * 16 + rr4;
                    int n = nw * 16 + nf * 8 + cc2;
                    *(uint32_t*)(smem + Pb + m * STP + n * 2) = pk[mf][nf][0];
                    *(uint32_t*)(smem + Pb + (m + 8) * STP + n * 2) = pk[mf][nf][1];
                }
            __threadfence_block();
            BAR_ARRIVE(3 + (i & 3), 512);                  // P[i&3] full
        }
    } else {
        // ============ group B: MMA2 ============
        stageVt_async(sb, V_O, g_vtf, jbase, t256);
        CP_COMMIT();

        float oacc[2][8][4];
#pragma unroll
        for (int a = 0; a < 2; a++)
#pragma unroll
            for (int b = 0; b < 8; b++)
#pragma unroll
                for (int c = 0; c < 4; c++) oacc[a][b][c] = 0.0f;

        const uint32_t aPb = sb + P_O + (uint32_t)(mw * 32) * STP + loA_P;
        const uint32_t bVb = sb + V_O + (uint32_t)(nw * 64) * STV + loB_V;

        for (int i = 0; i < NCHSEG; i++) {
            BAR_SYNC(3 + (i & 3), 512);                    // P[i&3] full
            CP_WAIT(0);
            BAR_SYNC(2, 256);                              // V[i&1] visible
            if (i + 1 < NCHSEG) {
                stageVt_async(sb, V_O + ((i + 1) & 1) * VBUF, g_vtf, jbase + (i + 1) * BJ, t256);
                CP_COMMIT();
            }

            const uint32_t aP = aPb + (uint32_t)((i & 3) * PBUF);
            const uint32_t bV = bVb + (uint32_t)((i & 1) * VBUF);
#pragma unroll
            for (int ks = 0; ks < 4; ks++) {
                const uint32_t ko = (uint32_t)(ks * 32);
                uint32_t p0[4], p1[4];
                ldsm4(p0, aP + ko);
                ldsm4(p1, aP + 16 * STP + ko);
#pragma unroll
                for (int t = 0; t < 4; t++) {
                    uint32_t bh[4];
                    ldsm4(bh, bV + (uint32_t)(t * 16) * STV + ko);
                    mma_f16(oacc[0][t * 2], p0, bh[0], bh[1]);
                    mma_f16(oacc[0][t * 2 + 1], p0, bh[2], bh[3]);
                    mma_f16(oacc[1][t * 2], p1, bh[0], bh[1]);
                    mma_f16(oacc[1][t * 2 + 1], p1, bh[2], bh[3]);
                }
            }
            BAR_ARRIVE(7 + (i & 3), 512);                  // P[i&3] empty
        }

        // epilogue: jseg 0 -> fp32 out ; jseg 1..7 -> fp16 partial
        if (blockIdx.y == 0) {
#pragma unroll
            for (int mf = 0; mf < 2; mf++)
#pragma unroll
                for (int j = 0; j < 8; j++) {
                    const float* c = oacc[mf][j];
                    int m = row0 + mw * 32 + mf * 16 + rr4;
                    int col = nw * 64 + (j >> 1) * 16 + (j & 1) * 8 + cc2;
                    *(float2*)(out + (size_t)m * HID + col) = make_float2(c[0], c[1]);
                    *(float2*)(out + (size_t)(m + 8) * HID + col) = make_float2(c[2], c[3]);
                }
        } else {
            __half* php = g_ph + (size_t)(blockIdx.y - 1) * NROWS * HID;
#pragma unroll
            for (int mf = 0; mf < 2; mf++)
#pragma unroll
                for (int j = 0; j < 8; j++) {
                    const float* c = oacc[mf][j];
                    int m = row0 + mw * 32 + mf * 16 + rr4;
                    int col = nw * 64 + (j >> 1) * 16 + (j & 1) * 8 + cc2;
                    *(uint32_t*)(php + (size_t)m * HID + col) = h2pack(c[0], c[1]);
                    *(uint32_t*)(php + (size_t)(m + 8) * HID + col) = h2pack(c[2], c[3]);
                }
        }
    }
}

// ---------------- deterministic reduce of fp16 partials ----------------
__global__ __launch_bounds__(NTHREADS)
void reduce_kernel(float* __restrict__ out)
{
    size_t i = ((size_t)blockIdx.x * NTHREADS + threadIdx.x) * 4;
    float4 a = *(float4*)(out + i);
#pragma unroll
    for (int s = 0; s < JSPLIT - 1; s++) {
        uint2 b = *(const uint2*)(g_ph + (size_t)s * NROWS * HID + i);
        __half2 h0 = *(__half2*)&b.x, h1 = *(__half2*)&b.y;
        float2 f0 = __half22float2(h0), f1 = __half22float2(h1);
        a.x += f0.x; a.y += f0.y; a.z += f1.x; a.w += f1.y;
    }
    *(float4*)(out + i) = a;
}

// ---------------------------------------------------------------------------
extern "C" void kernel_launch(void* const* d_in, const int* in_sizes, int n_in,
                              void* d_out, int out_size)
{
    const float* query = (const float*)d_in[0];
    const float* key_  = (const float*)d_in[1];
    const float* value = (const float*)d_in[2];
    const float* Wq = (const float*)d_in[3];
    const float* bq = (const float*)d_in[4];
    const float* Wk = (const float*)d_in[5];
    const float* bk = (const float*)d_in[6];
    const float* Wv = (const float*)d_in[7];
    const float* bv = (const float*)d_in[8];
    float* out = (float*)d_out;
    (void)in_sizes; (void)n_in; (void)out_size;

    __half *qf, *kf, *vtf;
    cudaGetSymbolAddress((void**)&qf, g_qf);
    cudaGetSymbolAddress((void**)&kf, g_kf);
    cudaGetSymbolAddress((void**)&vtf, g_vtf);

    wconv_kernel<<<dim3(HID * HID / 4 / NTHREADS, 3), NTHREADS>>>(Wq, Wk, Wv);

    cudaFuncSetAttribute(linear_hmma_kernel, cudaFuncAttributeMaxDynamicSharedMemorySize, LSMEMB);
    linear_hmma_kernel<<<dim3(NROWS / 64, 3), 512, LSMEMB>>>(
        query, key_, value, bq, bk, bv, qf, kf, vtf);

    cudaFuncSetAttribute(attn_kernel, cudaFuncAttributeMaxDynamicSharedMemorySize, SMEMB);
    attn_kernel<<<dim3(NROWS / 64, JSPLIT), 512, SMEMB>>>(out);

    reduce_kernel<<<NROWS * HID / 4 / NTHREADS, NTHREADS>>>(out);
}